// round 1
// baseline (speedup 1.0000x reference)
#include <cuda_runtime.h>
#include <math.h>

// Problem constants
constexpr int NB  = 4;
constexpr int NS  = 2048;
constexpr int NDV = 1024;
constexpr int NH  = 16;
constexpr int NDH = 64;
constexpr int NT  = 64;
constexpr int NDT = 768;

// Scratch (device globals: allocation-free rule)
__device__ float g_pool[NB * NDT];
__device__ float g_gate_q[NB * NDV];
__device__ float g_gate_k[NB * NDV];
__device__ float g_q[(size_t)NB * NH * NS * NDH];
__device__ float g_k[(size_t)NB * NH * NS * NDH];
__device__ float g_v[(size_t)NB * NH * NS * NDH];

// ---------------------------------------------------------------------------
// Kernel 1: masked-mean pool over text tokens.  pool[b,d]
// ---------------------------------------------------------------------------
__global__ void pool_kernel(const float* __restrict__ txt,
                            const float* __restrict__ tmask) {
    int i = blockIdx.x * blockDim.x + threadIdx.x;
    if (i >= NB * NDT) return;
    int b = i / NDT;
    int d = i - b * NDT;
    float s = 0.f, ms = 0.f;
#pragma unroll 4
    for (int t = 0; t < NT; ++t) {
        float mv = tmask[b * NT + t];
        s += txt[((size_t)(b * NT + t)) * NDT + d] * mv;
        ms += mv;
    }
    g_pool[i] = s / ms;
}

// ---------------------------------------------------------------------------
// Kernel 2: gates = 1 + sigmoid(pool @ Wd + bd).  blockIdx.y: 0 = q, 1 = k
// ---------------------------------------------------------------------------
__global__ void gate_kernel(const float* __restrict__ Wdq,
                            const float* __restrict__ bdq,
                            const float* __restrict__ Wdk,
                            const float* __restrict__ bdk) {
    int idx = blockIdx.x * blockDim.x + threadIdx.x;
    if (idx >= NB * NDV) return;
    int which = blockIdx.y;
    int b = idx / NDV;
    int n = idx - b * NDV;
    const float* W  = which ? Wdk : Wdq;
    const float* bb = which ? bdk : bdq;
    float acc = bb[n];
    const float* p = &g_pool[b * NDT];
#pragma unroll 4
    for (int d = 0; d < NDT; ++d)
        acc += p[d] * W[(size_t)d * NDV + n];
    float gate = 1.f + 1.f / (1.f + expf(-acc));
    if (which) g_gate_k[idx] = gate;
    else       g_gate_q[idx] = gate;
}

// ---------------------------------------------------------------------------
// Kernel 3: fused QKV projection.  out = (hid @ W + bias) * gate, written
// head-major [(b*H + h), s, d].  blockIdx.z selects q/k/v.
// Tile 128x128, 256 threads, 8x8 micro, K-chunk 16.
// ---------------------------------------------------------------------------
constexpr int GK = 16;

__global__ void __launch_bounds__(256) qkv_kernel(
        const float* __restrict__ hid,
        const float* __restrict__ Wq, const float* __restrict__ bq,
        const float* __restrict__ Wk, const float* __restrict__ bk,
        const float* __restrict__ Wv, const float* __restrict__ bv) {
    __shared__ float As[GK][132];   // transposed: As[k][m], padded pitch
    __shared__ float Bs[GK][128];   // Bs[k][n]

    const float* W;  const float* bias; const float* gate; float* out;
    int z = blockIdx.z;
    if (z == 0)      { W = Wq; bias = bq; gate = g_gate_q; out = g_q; }
    else if (z == 1) { W = Wk; bias = bk; gate = g_gate_k; out = g_k; }
    else             { W = Wv; bias = bv; gate = nullptr;  out = g_v; }

    int m0 = blockIdx.y * 128;
    int n0 = blockIdx.x * 128;
    int tid = threadIdx.x;
    int tx = tid & 15, ty = tid >> 4;

    float acc[8][8];
#pragma unroll
    for (int i = 0; i < 8; ++i)
#pragma unroll
        for (int j = 0; j < 8; ++j) acc[i][j] = 0.f;

    for (int k0 = 0; k0 < NDV; k0 += GK) {
        // A tile: 128 rows x 16 k  (store transposed)
#pragma unroll
        for (int u = 0; u < 2; ++u) {
            int idx = tid * 2 + u;          // 0..511 float4 slots
            int m  = idx >> 2;
            int ka = (idx & 3) * 4;
            float4 a = *(const float4*)&hid[(size_t)(m0 + m) * NDV + k0 + ka];
            As[ka + 0][m] = a.x;
            As[ka + 1][m] = a.y;
            As[ka + 2][m] = a.z;
            As[ka + 3][m] = a.w;
        }
        // B tile: 16 k x 128 n
#pragma unroll
        for (int u = 0; u < 2; ++u) {
            int idx = tid * 2 + u;
            int r  = idx >> 5;
            int c4 = (idx & 31) * 4;
            *(float4*)&Bs[r][c4] =
                *(const float4*)&W[(size_t)(k0 + r) * NDV + n0 + c4];
        }
        __syncthreads();
#pragma unroll
        for (int k = 0; k < GK; ++k) {
            float a[8], bb[8];
            *(float4*)(a)      = *(const float4*)(&As[k][ty * 8]);
            *(float4*)(a + 4)  = *(const float4*)(&As[k][ty * 8 + 4]);
            *(float4*)(bb)     = *(const float4*)(&Bs[k][tx * 8]);
            *(float4*)(bb + 4) = *(const float4*)(&Bs[k][tx * 8 + 4]);
#pragma unroll
            for (int i = 0; i < 8; ++i)
#pragma unroll
                for (int j = 0; j < 8; ++j)
                    acc[i][j] = fmaf(a[i], bb[j], acc[i][j]);
        }
        __syncthreads();
    }

    // Epilogue: bias + gate, write head-major
    int b = m0 >> 11;                      // 2048 rows per batch, 128 | 2048
    int n_base = n0 + tx * 8;
    int h  = n_base >> 6;
    int d0 = n_base & 63;
    float gv[8], bv8[8];
#pragma unroll
    for (int j = 0; j < 8; ++j) {
        gv[j]  = gate ? gate[b * NDV + n_base + j] : 1.f;
        bv8[j] = bias[n_base + j];
    }
#pragma unroll
    for (int i = 0; i < 8; ++i) {
        int m = m0 + ty * 8 + i;
        int srow = m & (NS - 1);
        float vals[8];
#pragma unroll
        for (int j = 0; j < 8; ++j)
            vals[j] = (acc[i][j] + bv8[j]) * gv[j];
        float* op = out + (((size_t)b * NH + h) * NS + srow) * NDH + d0;
        *(float4*)op       = *(float4*)vals;
        *(float4*)(op + 4) = *(float4*)(vals + 4);
    }
}

// ---------------------------------------------------------------------------
// Kernel 4: flash attention, fp32.  One block = (b,h) x 128 query rows.
// 128 threads (ty 0..15 x tx 0..7), 8x8 micro.  K-tile = 64.
// Writes final [B,S,H*Dh] directly to d_out.
// ---------------------------------------------------------------------------
constexpr int BQ = 128;
constexpr int BK = 64;
constexpr int PITCH = 65;
constexpr int ATTN_SMEM_FLOATS = BQ * PITCH + BK * PITCH + BK * PITCH + BQ * PITCH;
constexpr int ATTN_SMEM_BYTES  = ATTN_SMEM_FLOATS * 4;   // 99840

__global__ void __launch_bounds__(128) attn_kernel(
        const float* __restrict__ amask, float* __restrict__ out) {
    extern __shared__ float sm[];
    float* Qs = sm;                          // [BQ][PITCH]
    float* Ks = Qs + BQ * PITCH;             // [BK][PITCH]
    float* Vs = Ks + BK * PITCH;             // [BK][PITCH]
    float* Ps = Vs + BK * PITCH;             // [BQ][PITCH]

    int bh = blockIdx.y;
    int b = bh >> 4;
    int h = bh & 15;
    int q0 = blockIdx.x * BQ;
    int tid = threadIdx.x;
    int tx = tid & 7, ty = tid >> 3;

    const float* Qg = g_q + (size_t)bh * NS * NDH;
    const float* Kg = g_k + (size_t)bh * NS * NDH;
    const float* Vg = g_v + (size_t)bh * NS * NDH;

    // Load Q tile (128x64) into padded smem
#pragma unroll
    for (int u = 0; u < 16; ++u) {
        int idx = tid + u * 128;             // float4 slot 0..2047
        int r  = idx >> 4;
        int c4 = (idx & 15) * 4;
        float4 v = *(const float4*)&Qg[(size_t)(q0 + r) * NDH + c4];
        Qs[r * PITCH + c4 + 0] = v.x;
        Qs[r * PITCH + c4 + 1] = v.y;
        Qs[r * PITCH + c4 + 2] = v.z;
        Qs[r * PITCH + c4 + 3] = v.w;
    }

    float mrow[8], lrow[8], O[8][8];
#pragma unroll
    for (int i = 0; i < 8; ++i) {
        mrow[i] = -1e30f;
        lrow[i] = 0.f;
#pragma unroll
        for (int j = 0; j < 8; ++j) O[i][j] = 0.f;
    }

    for (int t0 = 0; t0 < NS; t0 += BK) {
        __syncthreads();   // prev iter's Ps/Ks/Vs reads done; Q ready (iter 0)
        // Load K,V tiles (64x64 each)
#pragma unroll
        for (int u = 0; u < 8; ++u) {
            int idx = tid + u * 128;
            int r  = idx >> 4;
            int c4 = (idx & 15) * 4;
            float4 kv = *(const float4*)&Kg[(size_t)(t0 + r) * NDH + c4];
            Ks[r * PITCH + c4 + 0] = kv.x;
            Ks[r * PITCH + c4 + 1] = kv.y;
            Ks[r * PITCH + c4 + 2] = kv.z;
            Ks[r * PITCH + c4 + 3] = kv.w;
            float4 vv = *(const float4*)&Vg[(size_t)(t0 + r) * NDH + c4];
            Vs[r * PITCH + c4 + 0] = vv.x;
            Vs[r * PITCH + c4 + 1] = vv.y;
            Vs[r * PITCH + c4 + 2] = vv.z;
            Vs[r * PITCH + c4 + 3] = vv.w;
        }
        __syncthreads();

        // S = Q @ K^T
        float sc[8][8];
#pragma unroll
        for (int i = 0; i < 8; ++i)
#pragma unroll
            for (int j = 0; j < 8; ++j) sc[i][j] = 0.f;
#pragma unroll 4
        for (int k = 0; k < BK; ++k) {
            float a[8], bb[8];
#pragma unroll
            for (int i = 0; i < 8; ++i) a[i]  = Qs[(ty * 8 + i) * PITCH + k];
#pragma unroll
            for (int j = 0; j < 8; ++j) bb[j] = Ks[(tx * 8 + j) * PITCH + k];
#pragma unroll
            for (int i = 0; i < 8; ++i)
#pragma unroll
                for (int j = 0; j < 8; ++j)
                    sc[i][j] = fmaf(a[i], bb[j], sc[i][j]);
        }

        // scale + additive mask; per-row tile max
        float mj[8];
#pragma unroll
        for (int j = 0; j < 8; ++j)
            mj[j] = amask[b * NS + t0 + tx * 8 + j];
        float mt[8];
#pragma unroll
        for (int i = 0; i < 8; ++i) {
            mt[i] = -1e30f;
#pragma unroll
            for (int j = 0; j < 8; ++j) {
                sc[i][j] = sc[i][j] * 0.125f + mj[j];
                mt[i] = fmaxf(mt[i], sc[i][j]);
            }
        }

        // online softmax update
#pragma unroll
        for (int i = 0; i < 8; ++i) {
#pragma unroll
            for (int off = 1; off < 8; off <<= 1)
                mt[i] = fmaxf(mt[i], __shfl_xor_sync(0xffffffffu, mt[i], off));
            float mn = fmaxf(mrow[i], mt[i]);
            float alpha = __expf(mrow[i] - mn);
            mrow[i] = mn;
            lrow[i] *= alpha;
#pragma unroll
            for (int j = 0; j < 8; ++j) O[i][j] *= alpha;
        }
#pragma unroll
        for (int i = 0; i < 8; ++i) {
            float rs = 0.f;
#pragma unroll
            for (int j = 0; j < 8; ++j) {
                float p = __expf(sc[i][j] - mrow[i]);
                sc[i][j] = p;
                rs += p;
            }
#pragma unroll
            for (int off = 1; off < 8; off <<= 1)
                rs += __shfl_xor_sync(0xffffffffu, rs, off);
            lrow[i] += rs;
#pragma unroll
            for (int j = 0; j < 8; ++j)
                Ps[(ty * 8 + i) * PITCH + tx * 8 + j] = sc[i][j];
        }
        __syncthreads();

        // O += P @ V
#pragma unroll 4
        for (int t = 0; t < BK; ++t) {
            float pp[8], vv[8];
#pragma unroll
            for (int i = 0; i < 8; ++i) pp[i] = Ps[(ty * 8 + i) * PITCH + t];
#pragma unroll
            for (int j = 0; j < 8; ++j) vv[j] = Vs[t * PITCH + tx * 8 + j];
#pragma unroll
            for (int i = 0; i < 8; ++i)
#pragma unroll
                for (int j = 0; j < 8; ++j)
                    O[i][j] = fmaf(pp[i], vv[j], O[i][j]);
        }
    }

    // Epilogue: normalize, write [B,S,H*Dh]
#pragma unroll
    for (int i = 0; i < 8; ++i) {
        float inv = 1.f / lrow[i];
        int srow = q0 + ty * 8 + i;
        float vals[8];
#pragma unroll
        for (int j = 0; j < 8; ++j) vals[j] = O[i][j] * inv;
        float* op = out + ((size_t)(b * NS + srow)) * NDV + h * NDH + tx * 8;
        *(float4*)op       = *(float4*)vals;
        *(float4*)(op + 4) = *(float4*)(vals + 4);
    }
}

// ---------------------------------------------------------------------------
// Launch
// ---------------------------------------------------------------------------
extern "C" void kernel_launch(void* const* d_in, const int* in_sizes, int n_in,
                              void* d_out, int out_size) {
    const float* hid   = (const float*)d_in[0];
    const float* amask = (const float*)d_in[1];
    const float* txt   = (const float*)d_in[2];
    const float* tmask = (const float*)d_in[3];
    const float* Wq  = (const float*)d_in[4];
    const float* bq  = (const float*)d_in[5];
    const float* Wk  = (const float*)d_in[6];
    const float* bk  = (const float*)d_in[7];
    const float* Wv  = (const float*)d_in[8];
    const float* bv  = (const float*)d_in[9];
    const float* Wdq = (const float*)d_in[10];
    const float* bdq = (const float*)d_in[11];
    const float* Wdk = (const float*)d_in[12];
    const float* bdk = (const float*)d_in[13];
    float* out = (float*)d_out;

    cudaFuncSetAttribute(attn_kernel,
                         cudaFuncAttributeMaxDynamicSharedMemorySize,
                         ATTN_SMEM_BYTES);

    pool_kernel<<<(NB * NDT + 255) / 256, 256>>>(txt, tmask);
    gate_kernel<<<dim3((NB * NDV + 255) / 256, 2), 256>>>(Wdq, bdq, Wdk, bdk);
    qkv_kernel<<<dim3(NDV / 128, (NB * NS) / 128, 3), 256>>>(
        hid, Wq, bq, Wk, bk, Wv, bv);
    attn_kernel<<<dim3(NS / BQ, NB * NH), 128, ATTN_SMEM_BYTES>>>(amask, out);
}

// round 4
// speedup vs baseline: 1.0816x; 1.0816x over previous
#include <cuda_runtime.h>
#include <cstdint>
#include <cstddef>
#include <math.h>

// Problem constants
constexpr int NB  = 4;
constexpr int NS  = 2048;
constexpr int NDV = 1024;
constexpr int NH  = 16;
constexpr int NDH = 64;
constexpr int NT  = 64;
constexpr int NDT = 768;

// Scratch (device globals: allocation-free rule)
__device__ float g_pool[NB * NDT];
__device__ float g_gate_q[NB * NDV];
__device__ float g_gate_k[NB * NDV];
__device__ float g_q[(size_t)NB * NH * NS * NDH];   // [bh][s][d]
__device__ float g_k[(size_t)NB * NH * NS * NDH];   // [bh][d][s]  (TRANSPOSED)
__device__ float g_v[(size_t)NB * NH * NS * NDH];   // [bh][s][d]

// ---------------------------------------------------------------------------
// cp.async helpers
// ---------------------------------------------------------------------------
__device__ __forceinline__ void cp_async16(void* smem_dst, const void* gmem_src) {
    unsigned int s = (unsigned int)__cvta_generic_to_shared(smem_dst);
    asm volatile("cp.async.cg.shared.global [%0], [%1], 16;\n" :: "r"(s), "l"(gmem_src));
}
__device__ __forceinline__ void cp_commit() {
    asm volatile("cp.async.commit_group;\n");
}
template <int N>
__device__ __forceinline__ void cp_wait() {
    asm volatile("cp.async.wait_group %0;\n" :: "n"(N));
}

// ---------------------------------------------------------------------------
// Kernel 1: masked-mean pool over text tokens.  pool[b,d]
// ---------------------------------------------------------------------------
__global__ void pool_kernel(const float* __restrict__ txt,
                            const float* __restrict__ tmask) {
    int i = blockIdx.x * blockDim.x + threadIdx.x;
    if (i >= NB * NDT) return;
    int b = i / NDT;
    int d = i - b * NDT;
    float s = 0.f, ms = 0.f;
#pragma unroll 4
    for (int t = 0; t < NT; ++t) {
        float mv = tmask[b * NT + t];
        s += txt[((size_t)(b * NT + t)) * NDT + d] * mv;
        ms += mv;
    }
    g_pool[i] = s / ms;
}

// ---------------------------------------------------------------------------
// Kernel 2: gates = 1 + sigmoid(pool @ Wd + bd).  blockIdx.y: 0 = q, 1 = k
// ---------------------------------------------------------------------------
__global__ void gate_kernel(const float* __restrict__ Wdq,
                            const float* __restrict__ bdq,
                            const float* __restrict__ Wdk,
                            const float* __restrict__ bdk) {
    int idx = blockIdx.x * blockDim.x + threadIdx.x;
    if (idx >= NB * NDV) return;
    int which = blockIdx.y;
    int b = idx / NDV;
    int n = idx - b * NDV;
    const float* W  = which ? Wdk : Wdq;
    const float* bb = which ? bdk : bdq;
    float acc = bb[n];
    const float* p = &g_pool[b * NDT];
#pragma unroll 4
    for (int d = 0; d < NDT; ++d)
        acc += p[d] * W[(size_t)d * NDV + n];
    float gate = 1.f + 1.f / (1.f + expf(-acc));
    if (which) g_gate_k[idx] = gate;
    else       g_gate_q[idx] = gate;
}

// ---------------------------------------------------------------------------
// Kernel 3: fused QKV projection with cp.async double buffering.
// out = (hid @ W + bias) * gate.  q,v written [bh][s][d]; k written [bh][d][s].
// Tile 128x128, 256 threads (tx 0..15, ty 0..15), 8x8 micro, K-chunk 16.
// ---------------------------------------------------------------------------
constexpr int GK  = 16;
constexpr int AP  = 20;    // As pitch (floats), mult of 4
constexpr int BP  = 132;   // Bs pitch (floats), mult of 4
constexpr int NCHUNK = NDV / GK;   // 64

__global__ void __launch_bounds__(256, 2) qkv_kernel(
        const float* __restrict__ hid,
        const float* __restrict__ Wq, const float* __restrict__ bq,
        const float* __restrict__ Wk, const float* __restrict__ bk,
        const float* __restrict__ Wv, const float* __restrict__ bv) {
    __shared__ float As[2][128 * AP];   // row-major [m][k]
    __shared__ float Bs[2][GK * BP];    // [k][n]

    const float* W;  const float* bias; const float* gate; float* out;
    int z = blockIdx.z;
    if (z == 0)      { W = Wq; bias = bq; gate = g_gate_q; out = g_q; }
    else if (z == 1) { W = Wk; bias = bk; gate = g_gate_k; out = g_k; }
    else             { W = Wv; bias = bv; gate = nullptr;  out = g_v; }

    int m0 = blockIdx.y * 128;
    int n0 = blockIdx.x * 128;
    int tid = threadIdx.x;
    int tx = tid & 15, ty = tid >> 4;

    // cp.async tile loader: 512 A-chunks + 512 B-chunks of 16B, 4 per thread
    auto issue_tile = [&](int c, int st) {
#pragma unroll
        for (int u = 0; u < 2; ++u) {
            int idx = tid * 2 + u;
            int ar  = idx >> 2;            // 0..127
            int ac4 = (idx & 3) * 4;       // 0,4,8,12
            cp_async16(&As[st][ar * AP + ac4],
                       &hid[(size_t)(m0 + ar) * NDV + c * GK + ac4]);
            int br  = idx >> 5;            // 0..15
            int bc4 = (idx & 31) * 4;      // 0..124
            cp_async16(&Bs[st][br * BP + bc4],
                       &W[(size_t)(c * GK + br) * NDV + n0 + bc4]);
        }
        cp_commit();
    };

    float acc[8][8];
#pragma unroll
    for (int i = 0; i < 8; ++i)
#pragma unroll
        for (int j = 0; j < 8; ++j) acc[i][j] = 0.f;

    issue_tile(0, 0);
    issue_tile(1, 1);

    for (int c = 0; c < NCHUNK; ++c) {
        if (c == NCHUNK - 1) cp_wait<0>(); else cp_wait<1>();
        __syncthreads();
        int st = c & 1;
        const float* Ap = &As[st][0];
        const float* Bp = &Bs[st][0];
#pragma unroll
        for (int k = 0; k < GK; ++k) {
            float a[8], bb[8];
#pragma unroll
            for (int i = 0; i < 8; ++i)
                a[i] = Ap[(ty * 8 + i) * AP + k];
            *(float4*)(bb)     = *(const float4*)(&Bp[k * BP + tx * 8]);
            *(float4*)(bb + 4) = *(const float4*)(&Bp[k * BP + tx * 8 + 4]);
#pragma unroll
            for (int i = 0; i < 8; ++i)
#pragma unroll
                for (int j = 0; j < 8; ++j)
                    acc[i][j] = fmaf(a[i], bb[j], acc[i][j]);
        }
        __syncthreads();
        if (c + 2 < NCHUNK) issue_tile(c + 2, st);
    }

    // Epilogue: bias + gate
    int b = m0 >> 11;                      // 2048 rows per batch
    int n_base = n0 + tx * 8;
    int h  = n_base >> 6;
    int d0 = n_base & 63;
    float gv[8], bv8[8];
#pragma unroll
    for (int j = 0; j < 8; ++j) {
        gv[j]  = gate ? gate[b * NDV + n_base + j] : 1.f;
        bv8[j] = bias[n_base + j];
    }
    if (z == 1) {
        // K: write transposed [bh][d][s] (scalar scatter)
        float* base = out + ((size_t)(b * NH + h) * NDH + d0) * NS;
#pragma unroll
        for (int i = 0; i < 8; ++i) {
            int srow = (m0 + ty * 8 + i) & (NS - 1);
#pragma unroll
            for (int j = 0; j < 8; ++j)
                base[(size_t)j * NS + srow] = (acc[i][j] + bv8[j]) * gv[j];
        }
    } else {
        // Q/V: [bh][s][d], vectorized
#pragma unroll
        for (int i = 0; i < 8; ++i) {
            int srow = (m0 + ty * 8 + i) & (NS - 1);
            float vals[8];
#pragma unroll
            for (int j = 0; j < 8; ++j)
                vals[j] = (acc[i][j] + bv8[j]) * gv[j];
            float* op = out + (((size_t)b * NH + h) * NS + srow) * NDH + d0;
            *(float4*)op       = *(float4*)vals;
            *(float4*)(op + 4) = *(float4*)(vals + 4);
        }
    }
}

// ---------------------------------------------------------------------------
// Kernel 4: flash attention, fp32, vectorized smem + shfl-based P@V.
// One block = (b,h) x 128 query rows.  128 threads (ty 0..15 x tx 0..7).
// Double-buffered cp.async K/V tiles.  Writes [B,S,H*Dh] to d_out.
// ---------------------------------------------------------------------------
constexpr int BQ = 128;
constexpr int BK = 64;
constexpr int NTILE = NS / BK;          // 32
constexpr int QP = 132;                 // Qt pitch (k-major), mult of 4
constexpr int KP = 68;                  // Kt pitch (k-major), mult of 4
constexpr int VP = 68;                  // Vt pitch (row-major), mult of 4
constexpr int ATTN_SMEM_FLOATS = NDH * QP + 2 * NDH * KP + 2 * BK * VP;
constexpr int ATTN_SMEM_BYTES  = ATTN_SMEM_FLOATS * 4;   // 103424

__global__ void __launch_bounds__(128, 2) attn_kernel(
        const float* __restrict__ amask, float* __restrict__ out) {
    extern __shared__ float sm[];
    float* Qt = sm;                         // [64][QP]   k-major Q
    float* Kt = Qt + NDH * QP;              // [2][64][KP] k-major K
    float* Vt = Kt + 2 * NDH * KP;          // [2][64][VP] row-major V

    int bh = blockIdx.y;
    int b  = bh >> 4;
    int q0 = blockIdx.x * BQ;
    int tid = threadIdx.x;
    int tx = tid & 7, ty = tid >> 3;

    const float* Qg = g_q + (size_t)bh * NS * NDH;
    const float* Kg = g_k + (size_t)bh * NDH * NS;   // [d][s]
    const float* Vg = g_v + (size_t)bh * NS * NDH;

    // K/V tile loader via cp.async: 16 chunks of 16B per thread
    auto issue_kv = [&](int t0, int st) {
#pragma unroll
        for (int u = 0; u < 8; ++u) {
            int idx = tid + u * 128;
            int row = idx >> 4;             // 0..63
            int c4  = (idx & 15) * 4;       // 0..60
            cp_async16(&Kt[(size_t)st * NDH * KP + row * KP + c4],
                       &Kg[(size_t)row * NS + t0 + c4]);
            cp_async16(&Vt[(size_t)st * BK * VP + row * VP + c4],
                       &Vg[(size_t)(t0 + row) * NDH + c4]);
        }
        cp_commit();
    };

    issue_kv(0, 0);
    issue_kv(BK, 1);

    // Load + transpose Q tile into k-major smem (one-time)
#pragma unroll
    for (int u = 0; u < 16; ++u) {
        int idx = tid + u * 128;
        int r  = idx >> 4;
        int c4 = (idx & 15) * 4;
        float4 v = *(const float4*)&Qg[(size_t)(q0 + r) * NDH + c4];
        Qt[(c4 + 0) * QP + r] = v.x;
        Qt[(c4 + 1) * QP + r] = v.y;
        Qt[(c4 + 2) * QP + r] = v.z;
        Qt[(c4 + 3) * QP + r] = v.w;
    }

    float mrow[8], lrow[8], O[8][8];
#pragma unroll
    for (int i = 0; i < 8; ++i) {
        mrow[i] = -1e30f;
        lrow[i] = 0.f;
#pragma unroll
        for (int j = 0; j < 8; ++j) O[i][j] = 0.f;
    }

    for (int it = 0; it < NTILE; ++it) {
        if (it == NTILE - 1) cp_wait<0>(); else cp_wait<1>();
        __syncthreads();                     // stage ready; Qt ready (it=0)
        int st = it & 1;
        const float* Kp = &Kt[(size_t)st * NDH * KP];
        const float* Vp = &Vt[(size_t)st * BK * VP];
        int t0 = it * BK;

        // S = Q @ K^T : both operands k-major, float4 loads
        float sc[8][8];
#pragma unroll
        for (int i = 0; i < 8; ++i)
#pragma unroll
            for (int j = 0; j < 8; ++j) sc[i][j] = 0.f;
#pragma unroll 8
        for (int k = 0; k < NDH; ++k) {
            float a[8], bb[8];
            *(float4*)(a)      = *(const float4*)(&Qt[k * QP + ty * 8]);
            *(float4*)(a + 4)  = *(const float4*)(&Qt[k * QP + ty * 8 + 4]);
            *(float4*)(bb)     = *(const float4*)(&Kp[k * KP + tx * 8]);
            *(float4*)(bb + 4) = *(const float4*)(&Kp[k * KP + tx * 8 + 4]);
#pragma unroll
            for (int i = 0; i < 8; ++i)
#pragma unroll
                for (int j = 0; j < 8; ++j)
                    sc[i][j] = fmaf(a[i], bb[j], sc[i][j]);
        }

        // scale + additive mask; per-row tile max
        float mj[8];
        *(float4*)(mj)     = *(const float4*)(&amask[b * NS + t0 + tx * 8]);
        *(float4*)(mj + 4) = *(const float4*)(&amask[b * NS + t0 + tx * 8 + 4]);
        float mt[8];
#pragma unroll
        for (int i = 0; i < 8; ++i) {
            mt[i] = -1e30f;
#pragma unroll
            for (int j = 0; j < 8; ++j) {
                sc[i][j] = sc[i][j] * 0.125f + mj[j];
                mt[i] = fmaxf(mt[i], sc[i][j]);
            }
        }

        // online softmax update (reduce over the 8-lane tx group)
#pragma unroll
        for (int i = 0; i < 8; ++i) {
#pragma unroll
            for (int off = 1; off < 8; off <<= 1)
                mt[i] = fmaxf(mt[i], __shfl_xor_sync(0xffffffffu, mt[i], off));
            float mn = fmaxf(mrow[i], mt[i]);
            float alpha = __expf(mrow[i] - mn);
            mrow[i] = mn;
            lrow[i] *= alpha;
#pragma unroll
            for (int j = 0; j < 8; ++j) O[i][j] *= alpha;
        }
#pragma unroll
        for (int i = 0; i < 8; ++i) {
            float rs = 0.f;
#pragma unroll
            for (int j = 0; j < 8; ++j) {
                float p = __expf(sc[i][j] - mrow[i]);
                sc[i][j] = p;
                rs += p;
            }
#pragma unroll
            for (int off = 1; off < 8; off <<= 1)
                rs += __shfl_xor_sync(0xffffffffu, rs, off);
            lrow[i] += rs;
        }

        // O += P @ V  via width-8 shuffle exchange of P (no smem round-trip)
#pragma unroll 8
        for (int tt = 0; tt < BK; ++tt) {
            float vv[8];
            *(float4*)(vv)     = *(const float4*)(&Vp[tt * VP + tx * 8]);
            *(float4*)(vv + 4) = *(const float4*)(&Vp[tt * VP + tx * 8 + 4]);
            int src = tt >> 3;
#pragma unroll
            for (int i = 0; i < 8; ++i) {
                float p = __shfl_sync(0xffffffffu, sc[i][tt & 7], src, 8);
#pragma unroll
                for (int j = 0; j < 8; ++j)
                    O[i][j] = fmaf(p, vv[j], O[i][j]);
            }
        }

        __syncthreads();                     // done reading stage st
        if (it + 2 < NTILE) issue_kv((it + 2) * BK, st);
    }

    // Epilogue: normalize, write [B,S,H*Dh]
    int h = bh & 15;
#pragma unroll
    for (int i = 0; i < 8; ++i) {
        float inv = 1.f / lrow[i];
        int srow = q0 + ty * 8 + i;
        float vals[8];
#pragma unroll
        for (int j = 0; j < 8; ++j) vals[j] = O[i][j] * inv;
        float* op = out + ((size_t)(b * NS + srow)) * NDV + h * NDH + tx * 8;
        *(float4*)op       = *(float4*)vals;
        *(float4*)(op + 4) = *(float4*)(vals + 4);
    }
}

// ---------------------------------------------------------------------------
// Launch
// ---------------------------------------------------------------------------
extern "C" void kernel_launch(void* const* d_in, const int* in_sizes, int n_in,
                              void* d_out, int out_size) {
    const float* hid   = (const float*)d_in[0];
    const float* amask = (const float*)d_in[1];
    const float* txt   = (const float*)d_in[2];
    const float* tmask = (const float*)d_in[3];
    const float* Wq  = (const float*)d_in[4];
    const float* bq  = (const float*)d_in[5];
    const float* Wk  = (const float*)d_in[6];
    const float* bk  = (const float*)d_in[7];
    const float* Wv  = (const float*)d_in[8];
    const float* bv  = (const float*)d_in[9];
    const float* Wdq = (const float*)d_in[10];
    const float* bdq = (const float*)d_in[11];
    const float* Wdk = (const float*)d_in[12];
    const float* bdk = (const float*)d_in[13];
    float* out = (float*)d_out;

    cudaFuncSetAttribute(attn_kernel,
                         cudaFuncAttributeMaxDynamicSharedMemorySize,
                         ATTN_SMEM_BYTES);

    pool_kernel<<<(NB * NDT + 255) / 256, 256>>>(txt, tmask);
    gate_kernel<<<dim3((NB * NDV + 255) / 256, 2), 256>>>(Wdq, bdq, Wdk, bdk);
    qkv_kernel<<<dim3(NDV / 128, (NB * NS) / 128, 3), 256>>>(
        hid, Wq, bq, Wk, bk, Wv, bv);
    attn_kernel<<<dim3(NS / BQ, NB * NH), 128, ATTN_SMEM_BYTES>>>(amask, out);
}

// round 6
// speedup vs baseline: 1.6925x; 1.5647x over previous
#include <cuda_runtime.h>
#include <cstdint>
#include <cstddef>
#include <math.h>

// Problem constants
constexpr int NB  = 4;
constexpr int NS  = 2048;
constexpr int NDV = 1024;
constexpr int NH  = 16;
constexpr int NDH = 64;
constexpr int NT  = 64;
constexpr int NDT = 768;

// Scratch (device globals: allocation-free rule)
__device__ float g_pool[NB * NDT];
__device__ float g_gate_q[NB * NDV];
__device__ float g_gate_k[NB * NDV];
__device__ float g_q[(size_t)NB * NH * NS * NDH];   // [bh][s][d]
__device__ float g_k[(size_t)NB * NH * NS * NDH];   // [bh][s][d]
__device__ float g_v[(size_t)NB * NH * NS * NDH];   // [bh][d][s]  (TRANSPOSED)

// ---------------------------------------------------------------------------
// helpers
// ---------------------------------------------------------------------------
__device__ __forceinline__ void cp_async16(void* smem_dst, const void* gmem_src) {
    unsigned int s = (unsigned int)__cvta_generic_to_shared(smem_dst);
    asm volatile("cp.async.cg.shared.global [%0], [%1], 16;\n" :: "r"(s), "l"(gmem_src));
}
__device__ __forceinline__ void cp_commit() {
    asm volatile("cp.async.commit_group;\n");
}
template <int N>
__device__ __forceinline__ void cp_wait() {
    asm volatile("cp.async.wait_group %0;\n" :: "n"(N));
}
// tf32 round: PTX cvt.rna.tf32.f32 needs a .b32 destination register
__device__ __forceinline__ float to_tf32(float x) {
    unsigned r;
    asm("cvt.rna.tf32.f32 %0, %1;" : "=r"(r) : "f"(x));
    return __uint_as_float(r);
}
// D += A*B, m16n8k8 tf32
__device__ __forceinline__ void mma_tf32(float* c, const unsigned* a,
                                         unsigned b0, unsigned b1) {
    asm volatile(
        "mma.sync.aligned.m16n8k8.row.col.f32.tf32.tf32.f32 "
        "{%0,%1,%2,%3}, {%4,%5,%6,%7}, {%8,%9}, {%0,%1,%2,%3};\n"
        : "+f"(c[0]), "+f"(c[1]), "+f"(c[2]), "+f"(c[3])
        : "r"(a[0]), "r"(a[1]), "r"(a[2]), "r"(a[3]), "r"(b0), "r"(b1));
}

// ---------------------------------------------------------------------------
// Kernel 1: masked-mean pool over text tokens.  pool[b,d]
// ---------------------------------------------------------------------------
__global__ void pool_kernel(const float* __restrict__ txt,
                            const float* __restrict__ tmask) {
    int i = blockIdx.x * blockDim.x + threadIdx.x;
    if (i >= NB * NDT) return;
    int b = i / NDT;
    int d = i - b * NDT;
    float s = 0.f, ms = 0.f;
#pragma unroll 4
    for (int t = 0; t < NT; ++t) {
        float mv = tmask[b * NT + t];
        s += txt[((size_t)(b * NT + t)) * NDT + d] * mv;
        ms += mv;
    }
    g_pool[i] = s / ms;
}

// ---------------------------------------------------------------------------
// Kernel 2: gates = 1 + sigmoid(pool @ Wd + bd).  blockIdx.y: 0 = q, 1 = k
// ---------------------------------------------------------------------------
__global__ void gate_kernel(const float* __restrict__ Wdq,
                            const float* __restrict__ bdq,
                            const float* __restrict__ Wdk,
                            const float* __restrict__ bdk) {
    int idx = blockIdx.x * blockDim.x + threadIdx.x;
    if (idx >= NB * NDV) return;
    int which = blockIdx.y;
    int b = idx / NDV;
    int n = idx - b * NDV;
    const float* W  = which ? Wdk : Wdq;
    const float* bb = which ? bdk : bdq;
    float acc = bb[n];
    const float* p = &g_pool[b * NDT];
#pragma unroll 4
    for (int d = 0; d < NDT; ++d)
        acc += p[d] * W[(size_t)d * NDV + n];
    float gate = 1.f + 1.f / (1.f + expf(-acc));
    if (which) g_gate_k[idx] = gate;
    else       g_gate_q[idx] = gate;
}

// ---------------------------------------------------------------------------
// Kernel 3: fused QKV projection with cp.async double buffering.
// out = (hid @ W + bias) * gate, rounded to tf32.
// q,k written [bh][s][d]; v written [bh][d][s] (transposed for PV mma).
// ---------------------------------------------------------------------------
constexpr int GK  = 16;
constexpr int AP  = 20;    // As pitch (floats)
constexpr int BP  = 132;   // Bs pitch (floats)
constexpr int NCHUNK = NDV / GK;   // 64

__global__ void __launch_bounds__(256, 2) qkv_kernel(
        const float* __restrict__ hid,
        const float* __restrict__ Wq, const float* __restrict__ bq,
        const float* __restrict__ Wk, const float* __restrict__ bk,
        const float* __restrict__ Wv, const float* __restrict__ bv) {
    __shared__ float As[2][128 * AP];   // row-major [m][k]
    __shared__ float Bs[2][GK * BP];    // [k][n]

    const float* W;  const float* bias; const float* gate; float* out;
    int z = blockIdx.z;
    if (z == 0)      { W = Wq; bias = bq; gate = g_gate_q; out = g_q; }
    else if (z == 1) { W = Wk; bias = bk; gate = g_gate_k; out = g_k; }
    else             { W = Wv; bias = bv; gate = nullptr;  out = g_v; }

    int m0 = blockIdx.y * 128;
    int n0 = blockIdx.x * 128;
    int tid = threadIdx.x;
    int tx = tid & 15, ty = tid >> 4;

    auto issue_tile = [&](int c, int st) {
#pragma unroll
        for (int u = 0; u < 2; ++u) {
            int idx = tid * 2 + u;
            int ar  = idx >> 2;
            int ac4 = (idx & 3) * 4;
            cp_async16(&As[st][ar * AP + ac4],
                       &hid[(size_t)(m0 + ar) * NDV + c * GK + ac4]);
            int br  = idx >> 5;
            int bc4 = (idx & 31) * 4;
            cp_async16(&Bs[st][br * BP + bc4],
                       &W[(size_t)(c * GK + br) * NDV + n0 + bc4]);
        }
        cp_commit();
    };

    float acc[8][8];
#pragma unroll
    for (int i = 0; i < 8; ++i)
#pragma unroll
        for (int j = 0; j < 8; ++j) acc[i][j] = 0.f;

    issue_tile(0, 0);
    issue_tile(1, 1);

    for (int c = 0; c < NCHUNK; ++c) {
        if (c == NCHUNK - 1) cp_wait<0>(); else cp_wait<1>();
        __syncthreads();
        int st = c & 1;
        const float* Ap = &As[st][0];
        const float* Bp = &Bs[st][0];
#pragma unroll
        for (int k = 0; k < GK; ++k) {
            float a[8], bb[8];
#pragma unroll
            for (int i = 0; i < 8; ++i)
                a[i] = Ap[(ty * 8 + i) * AP + k];
            *(float4*)(bb)     = *(const float4*)(&Bp[k * BP + tx * 8]);
            *(float4*)(bb + 4) = *(const float4*)(&Bp[k * BP + tx * 8 + 4]);
#pragma unroll
            for (int i = 0; i < 8; ++i)
#pragma unroll
                for (int j = 0; j < 8; ++j)
                    acc[i][j] = fmaf(a[i], bb[j], acc[i][j]);
        }
        __syncthreads();
        if (c + 2 < NCHUNK) issue_tile(c + 2, st);
    }

    // Epilogue: bias + gate, round to tf32 (attention consumes via tf32 mma)
    int b = m0 >> 11;
    int n_base = n0 + tx * 8;
    int h  = n_base >> 6;
    int d0 = n_base & 63;
    float gv[8], bv8[8];
#pragma unroll
    for (int j = 0; j < 8; ++j) {
        gv[j]  = gate ? gate[b * NDV + n_base + j] : 1.f;
        bv8[j] = bias[n_base + j];
    }
    if (z == 2) {
        // V: write transposed [bh][d][s] (scalar scatter)
        float* base = out + ((size_t)(b * NH + h) * NDH + d0) * NS;
#pragma unroll
        for (int i = 0; i < 8; ++i) {
            int srow = (m0 + ty * 8 + i) & (NS - 1);
#pragma unroll
            for (int j = 0; j < 8; ++j)
                base[(size_t)j * NS + srow] = to_tf32((acc[i][j] + bv8[j]) * gv[j]);
        }
    } else {
        // Q/K: [bh][s][d], vectorized
#pragma unroll
        for (int i = 0; i < 8; ++i) {
            int srow = (m0 + ty * 8 + i) & (NS - 1);
            float vals[8];
#pragma unroll
            for (int j = 0; j < 8; ++j)
                vals[j] = to_tf32((acc[i][j] + bv8[j]) * gv[j]);
            float* op = out + (((size_t)b * NH + h) * NS + srow) * NDH + d0;
            *(float4*)op       = *(float4*)vals;
            *(float4*)(op + 4) = *(float4*)(vals + 4);
        }
    }
}

// ---------------------------------------------------------------------------
// Kernel 4: flash attention with tf32 mma.sync tensor cores.
// Block = 128 threads (4 warps), BQ=64 q-rows (16 per warp), BK=64.
// Q,K smem row-major [s][d]; V smem transposed [d][s]; P per-warp smem tile.
// Double-buffered cp.async K/V.  Writes [B,S,H*Dh] to d_out.
// ---------------------------------------------------------------------------
constexpr int BQ = 64;
constexpr int BK = 64;
constexpr int NTILE = NS / BK;          // 32
constexpr int QP = 68;
constexpr int KP = 68;
constexpr int VP = 68;
constexpr int PP = 68;
constexpr int ATTN_SMEM_FLOATS =
    BQ * QP + 2 * BK * KP + 2 * NDH * VP + 4 * 16 * PP;
constexpr int ATTN_SMEM_BYTES = ATTN_SMEM_FLOATS * 4;   // 104448

__global__ void __launch_bounds__(128, 2) attn_kernel(
        const float* __restrict__ amask, float* __restrict__ out) {
    extern __shared__ float sm[];
    float* Qs = sm;                           // [BQ][QP]
    float* Ks = Qs + BQ * QP;                 // [2][BK][KP]  (token-major)
    float* Vs = Ks + 2 * BK * KP;             // [2][NDH][VP] (d-major = V^T)
    float* Ps = Vs + 2 * NDH * VP;            // [4 warps][16][PP]

    int bh = blockIdx.y;
    int b  = bh >> 4;
    int h  = bh & 15;
    int q0 = blockIdx.x * BQ;
    int tid  = threadIdx.x;
    int w    = tid >> 5;
    int lane = tid & 31;
    int gid  = lane >> 2;     // groupID (0..7)
    int tig  = lane & 3;      // thread-in-group (0..3)

    const float* Qg = g_q + (size_t)bh * NS * NDH;
    const float* Kg = g_k + (size_t)bh * NS * NDH;
    const float* Vg = g_v + (size_t)bh * NDH * NS;   // [d][s]

    auto issue_kv = [&](int t0, int st) {
#pragma unroll
        for (int u = 0; u < 8; ++u) {
            int idx = tid + u * 128;          // 0..1023
            int row = idx >> 4;               // 0..63
            int c4  = (idx & 15) * 4;         // 0..60
            cp_async16(&Ks[(size_t)st * BK * KP + row * KP + c4],
                       &Kg[(size_t)(t0 + row) * NDH + c4]);
            cp_async16(&Vs[(size_t)st * NDH * VP + row * VP + c4],
                       &Vg[(size_t)row * NS + t0 + c4]);
        }
        cp_commit();
    };

    issue_kv(0, 0);
    issue_kv(BK, 1);

    // Q tile: 64x64, direct row-major copy
#pragma unroll
    for (int u = 0; u < 8; ++u) {
        int idx = tid + u * 128;
        int r  = idx >> 4;
        int c4 = (idx & 15) * 4;
        *(float4*)&Qs[r * QP + c4] = *(const float4*)&Qg[(size_t)(q0 + r) * NDH + c4];
    }

    float o[8][4];
#pragma unroll
    for (int j = 0; j < 8; ++j)
#pragma unroll
        for (int r = 0; r < 4; ++r) o[j][r] = 0.f;
    float mrow[2] = {-1e30f, -1e30f};
    float lrow[2] = {0.f, 0.f};
    float* Pw = Ps + w * 16 * PP;
    int qrow = w * 16 + gid;                  // local q row (A-frag base)

    for (int it = 0; it < NTILE; ++it) {
        if (it == NTILE - 1) cp_wait<0>(); else cp_wait<1>();
        __syncthreads();
        int st = it & 1;
        const float* Kp = &Ks[(size_t)st * BK * KP];
        const float* Vp = &Vs[(size_t)st * NDH * VP];
        int t0 = it * BK;

        // A fragments of Q (reused across all 8 n-tiles)
        unsigned a[8][4];
#pragma unroll
        for (int kk = 0; kk < 8; ++kk) {
            a[kk][0] = __float_as_uint(Qs[qrow * QP + kk * 8 + tig]);
            a[kk][1] = __float_as_uint(Qs[(qrow + 8) * QP + kk * 8 + tig]);
            a[kk][2] = __float_as_uint(Qs[qrow * QP + kk * 8 + tig + 4]);
            a[kk][3] = __float_as_uint(Qs[(qrow + 8) * QP + kk * 8 + tig + 4]);
        }

        // S = Q @ K^T  (warp: 16 x 64)
        float s[8][4];
#pragma unroll
        for (int nt = 0; nt < 8; ++nt) {
            s[nt][0] = s[nt][1] = s[nt][2] = s[nt][3] = 0.f;
#pragma unroll
            for (int kk = 0; kk < 8; ++kk) {
                unsigned b0 = __float_as_uint(Kp[(nt * 8 + gid) * KP + kk * 8 + tig]);
                unsigned b1 = __float_as_uint(Kp[(nt * 8 + gid) * KP + kk * 8 + tig + 4]);
                mma_tf32(s[nt], a[kk], b0, b1);
            }
        }

        // scale + mask, per-row tile max (rows r=qrow and r+8)
        float mt0 = -1e30f, mt1 = -1e30f;
#pragma unroll
        for (int nt = 0; nt < 8; ++nt) {
            float2 mk = *(const float2*)&amask[b * NS + t0 + nt * 8 + 2 * tig];
            s[nt][0] = fmaf(s[nt][0], 0.125f, mk.x);
            s[nt][1] = fmaf(s[nt][1], 0.125f, mk.y);
            s[nt][2] = fmaf(s[nt][2], 0.125f, mk.x);
            s[nt][3] = fmaf(s[nt][3], 0.125f, mk.y);
            mt0 = fmaxf(mt0, fmaxf(s[nt][0], s[nt][1]));
            mt1 = fmaxf(mt1, fmaxf(s[nt][2], s[nt][3]));
        }
        // reduce over the quad (4 lanes share each row)
        mt0 = fmaxf(mt0, __shfl_xor_sync(0xffffffffu, mt0, 1));
        mt0 = fmaxf(mt0, __shfl_xor_sync(0xffffffffu, mt0, 2));
        mt1 = fmaxf(mt1, __shfl_xor_sync(0xffffffffu, mt1, 1));
        mt1 = fmaxf(mt1, __shfl_xor_sync(0xffffffffu, mt1, 2));

        float mn0 = fmaxf(mrow[0], mt0);
        float mn1 = fmaxf(mrow[1], mt1);
        float al0 = __expf(mrow[0] - mn0);
        float al1 = __expf(mrow[1] - mn1);
        mrow[0] = mn0; mrow[1] = mn1;
        lrow[0] *= al0; lrow[1] *= al1;
#pragma unroll
        for (int j = 0; j < 8; ++j) {
            o[j][0] *= al0; o[j][1] *= al0;
            o[j][2] *= al1; o[j][3] *= al1;
        }

        // exp (tf32-rounded so l-sum matches PV numerator), row sums, P->smem
        float rs0 = 0.f, rs1 = 0.f;
#pragma unroll
        for (int nt = 0; nt < 8; ++nt) {
            float p0 = to_tf32(__expf(s[nt][0] - mrow[0]));
            float p1 = to_tf32(__expf(s[nt][1] - mrow[0]));
            float p2 = to_tf32(__expf(s[nt][2] - mrow[1]));
            float p3 = to_tf32(__expf(s[nt][3] - mrow[1]));
            rs0 += p0 + p1;
            rs1 += p2 + p3;
            *(float2*)&Pw[gid * PP + nt * 8 + 2 * tig]       = make_float2(p0, p1);
            *(float2*)&Pw[(gid + 8) * PP + nt * 8 + 2 * tig] = make_float2(p2, p3);
        }
        rs0 += __shfl_xor_sync(0xffffffffu, rs0, 1);
        rs0 += __shfl_xor_sync(0xffffffffu, rs0, 2);
        rs1 += __shfl_xor_sync(0xffffffffu, rs1, 1);
        rs1 += __shfl_xor_sync(0xffffffffu, rs1, 2);
        lrow[0] += rs0;
        lrow[1] += rs1;
        __syncwarp();

        // O += P @ V  (A = P from smem, B = V^T from smem)
        unsigned pa[8][4];
#pragma unroll
        for (int kk = 0; kk < 8; ++kk) {
            pa[kk][0] = __float_as_uint(Pw[gid * PP + kk * 8 + tig]);
            pa[kk][1] = __float_as_uint(Pw[(gid + 8) * PP + kk * 8 + tig]);
            pa[kk][2] = __float_as_uint(Pw[gid * PP + kk * 8 + tig + 4]);
            pa[kk][3] = __float_as_uint(Pw[(gid + 8) * PP + kk * 8 + tig + 4]);
        }
#pragma unroll
        for (int j = 0; j < 8; ++j) {
#pragma unroll
            for (int kk = 0; kk < 8; ++kk) {
                unsigned b0 = __float_as_uint(Vp[(j * 8 + gid) * VP + kk * 8 + tig]);
                unsigned b1 = __float_as_uint(Vp[(j * 8 + gid) * VP + kk * 8 + tig + 4]);
                mma_tf32(o[j], pa[kk], b0, b1);
            }
        }

        __syncthreads();
        if (it + 2 < NTILE) issue_kv((it + 2) * BK, st);
    }

    // Epilogue: normalize, write [B,S,H*Dh]
    float inv0 = 1.f / lrow[0];
    float inv1 = 1.f / lrow[1];
    int r0 = q0 + qrow;                       // global q row (first half)
#pragma unroll
    for (int j = 0; j < 8; ++j) {
        int col = h * NDH + j * 8 + 2 * tig;
        *(float2*)&out[((size_t)(b * NS + r0)) * NDV + col] =
            make_float2(o[j][0] * inv0, o[j][1] * inv0);
        *(float2*)&out[((size_t)(b * NS + r0 + 8)) * NDV + col] =
            make_float2(o[j][2] * inv1, o[j][3] * inv1);
    }
}

// ---------------------------------------------------------------------------
// Launch
// ---------------------------------------------------------------------------
extern "C" void kernel_launch(void* const* d_in, const int* in_sizes, int n_in,
                              void* d_out, int out_size) {
    const float* hid   = (const float*)d_in[0];
    const float* amask = (const float*)d_in[1];
    const float* txt   = (const float*)d_in[2];
    const float* tmask = (const float*)d_in[3];
    const float* Wq  = (const float*)d_in[4];
    const float* bq  = (const float*)d_in[5];
    const float* Wk  = (const float*)d_in[6];
    const float* bk  = (const float*)d_in[7];
    const float* Wv  = (const float*)d_in[8];
    const float* bv  = (const float*)d_in[9];
    const float* Wdq = (const float*)d_in[10];
    const float* bdq = (const float*)d_in[11];
    const float* Wdk = (const float*)d_in[12];
    const float* bdk = (const float*)d_in[13];
    float* out = (float*)d_out;

    cudaFuncSetAttribute(attn_kernel,
                         cudaFuncAttributeMaxDynamicSharedMemorySize,
                         ATTN_SMEM_BYTES);

    pool_kernel<<<(NB * NDT + 255) / 256, 256>>>(txt, tmask);
    gate_kernel<<<dim3((NB * NDV + 255) / 256, 2), 256>>>(Wdq, bdq, Wdk, bdk);
    qkv_kernel<<<dim3(NDV / 128, (NB * NS) / 128, 3), 256>>>(
        hid, Wq, bq, Wk, bk, Wv, bv);
    attn_kernel<<<dim3(NS / BQ, NB * NH), 128, ATTN_SMEM_BYTES>>>(amask, out);
}

// round 7
// speedup vs baseline: 2.7918x; 1.6496x over previous
#include <cuda_runtime.h>
#include <cstdint>
#include <cstddef>
#include <math.h>

// Problem constants
constexpr int NB  = 4;
constexpr int NS  = 2048;
constexpr int NDV = 1024;
constexpr int NH  = 16;
constexpr int NDH = 64;
constexpr int NT  = 64;
constexpr int NDT = 768;

// Scratch (device globals: allocation-free rule)
__device__ float g_pool[NB * NDT];
__device__ float g_gate_q[NB * NDV];
__device__ float g_gate_k[NB * NDV];
__device__ float g_wt[(size_t)3 * NDV * NDV];        // [z][nout][k], tf32
__device__ float g_q[(size_t)NB * NH * NS * NDH];   // [bh][s][d]
__device__ float g_k[(size_t)NB * NH * NS * NDH];   // [bh][s][d]
__device__ float g_v[(size_t)NB * NH * NS * NDH];   // [bh][d][s]  (TRANSPOSED)

// ---------------------------------------------------------------------------
// helpers
// ---------------------------------------------------------------------------
__device__ __forceinline__ void cp_async16(void* smem_dst, const void* gmem_src) {
    unsigned int s = (unsigned int)__cvta_generic_to_shared(smem_dst);
    asm volatile("cp.async.cg.shared.global [%0], [%1], 16;\n" :: "r"(s), "l"(gmem_src));
}
__device__ __forceinline__ void cp_commit() {
    asm volatile("cp.async.commit_group;\n");
}
template <int N>
__device__ __forceinline__ void cp_wait() {
    asm volatile("cp.async.wait_group %0;\n" :: "n"(N));
}
// tf32 round (PTX cvt.rna.tf32.f32 needs a .b32 destination)
__device__ __forceinline__ float to_tf32(float x) {
    unsigned r;
    asm("cvt.rna.tf32.f32 %0, %1;" : "=r"(r) : "f"(x));
    return __uint_as_float(r);
}
__device__ __forceinline__ unsigned to_tf32_u(float x) {
    unsigned r;
    asm("cvt.rna.tf32.f32 %0, %1;" : "=r"(r) : "f"(x));
    return r;
}
// D += A*B, m16n8k8 tf32
__device__ __forceinline__ void mma_tf32(float* c, const unsigned* a,
                                         unsigned b0, unsigned b1) {
    asm volatile(
        "mma.sync.aligned.m16n8k8.row.col.f32.tf32.tf32.f32 "
        "{%0,%1,%2,%3}, {%4,%5,%6,%7}, {%8,%9}, {%0,%1,%2,%3};\n"
        : "+f"(c[0]), "+f"(c[1]), "+f"(c[2]), "+f"(c[3])
        : "r"(a[0]), "r"(a[1]), "r"(a[2]), "r"(a[3]), "r"(b0), "r"(b1));
}

// ---------------------------------------------------------------------------
// Kernel 0: weight transpose  g_wt[z][n][k] = to_tf32(W_z[k][n])
// ---------------------------------------------------------------------------
__global__ void wt_kernel(const float* __restrict__ Wq,
                          const float* __restrict__ Wk,
                          const float* __restrict__ Wv) {
    __shared__ float t[32][33];
    int z = blockIdx.z;
    const float* W = (z == 0) ? Wq : (z == 1) ? Wk : Wv;
    float* out = g_wt + (size_t)z * NDV * NDV;
    int k0 = blockIdx.x * 32, n0 = blockIdx.y * 32;
    int x = threadIdx.x, y = threadIdx.y;       // 32 x 8
#pragma unroll
    for (int i = 0; i < 32; i += 8)
        t[y + i][x] = W[(size_t)(k0 + y + i) * NDV + n0 + x];
    __syncthreads();
#pragma unroll
    for (int i = 0; i < 32; i += 8)
        out[(size_t)(n0 + y + i) * NDV + k0 + x] = to_tf32(t[x][y + i]);
}

// ---------------------------------------------------------------------------
// Kernel 1: masked-mean pool over text tokens.  pool[b,d]
// ---------------------------------------------------------------------------
__global__ void pool_kernel(const float* __restrict__ txt,
                            const float* __restrict__ tmask) {
    int i = blockIdx.x * blockDim.x + threadIdx.x;
    if (i >= NB * NDT) return;
    int b = i / NDT;
    int d = i - b * NDT;
    float s = 0.f, ms = 0.f;
#pragma unroll 4
    for (int t = 0; t < NT; ++t) {
        float mv = tmask[b * NT + t];
        s += txt[((size_t)(b * NT + t)) * NDT + d] * mv;
        ms += mv;
    }
    g_pool[i] = s / ms;
}

// ---------------------------------------------------------------------------
// Kernel 2: gates = 1 + sigmoid(pool @ Wd + bd).  blockIdx.y: 0 = q, 1 = k
// ---------------------------------------------------------------------------
__global__ void gate_kernel(const float* __restrict__ Wdq,
                            const float* __restrict__ bdq,
                            const float* __restrict__ Wdk,
                            const float* __restrict__ bdk) {
    int idx = blockIdx.x * blockDim.x + threadIdx.x;
    if (idx >= NB * NDV) return;
    int which = blockIdx.y;
    int b = idx / NDV;
    int n = idx - b * NDV;
    const float* W  = which ? Wdk : Wdq;
    const float* bb = which ? bdk : bdq;
    float acc = bb[n];
    const float* p = &g_pool[b * NDT];
#pragma unroll 4
    for (int d = 0; d < NDT; ++d)
        acc += p[d] * W[(size_t)d * NDV + n];
    float gate = 1.f + 1.f / (1.f + expf(-acc));
    if (which) g_gate_k[idx] = gate;
    else       g_gate_q[idx] = gate;
}

// ---------------------------------------------------------------------------
// Kernel 3: QKV projection via tf32 mma.sync.
// C[token][nout] = hid @ W  (A = hid [token][k] row-major,
//                            B = g_wt [nout][k] "col-major" = row.col mma).
// Block: 128 token x 128 nout, BK=16, 256 thr, 8 warps (4 m x 2 n),
// warp tile 32x64.  Double-buffered cp.async.
// out = to_tf32((C + bias) * gate); q,k -> [bh][s][d], v -> [bh][d][s].
// ---------------------------------------------------------------------------
constexpr int QBK = 16;
constexpr int QPT = 20;                     // smem pitch (20 = 4 mod 32: frag-read conflict-free)
constexpr int QNIT = NDV / QBK;             // 64

__global__ void __launch_bounds__(256) qkv_kernel(
        const float* __restrict__ hid,
        const float* __restrict__ bq,
        const float* __restrict__ bk,
        const float* __restrict__ bv) {
    __shared__ float As[2][128 * QPT];      // hid tile  [token][k]
    __shared__ float Bs[2][128 * QPT];      // Wt tile   [nout][k]

    int z = blockIdx.z;
    const float* Wt = g_wt + (size_t)z * NDV * NDV;
    const float* bias = (z == 0) ? bq : (z == 1) ? bk : bv;
    const float* gate = (z == 0) ? g_gate_q : (z == 1) ? g_gate_k : nullptr;
    float* out = (z == 0) ? g_q : (z == 1) ? g_k : g_v;

    int m0 = blockIdx.y * 128;              // token base
    int n0 = blockIdx.x * 128;              // nout base
    int tid  = threadIdx.x;
    int warp = tid >> 5;
    int lane = tid & 31;
    int gid  = lane >> 2;
    int tig  = lane & 3;
    int wm = warp & 3;                      // 0..3 (token)
    int wn = warp >> 2;                     // 0..1 (nout)

    auto issue = [&](int c, int st) {
#pragma unroll
        for (int u = 0; u < 2; ++u) {
            int idx = tid * 2 + u;          // 0..511
            int row = idx >> 2;             // 0..127
            int c4  = (idx & 3) * 4;        // 0,4,8,12
            cp_async16(&As[st][row * QPT + c4],
                       &hid[(size_t)(m0 + row) * NDV + c * QBK + c4]);
            cp_async16(&Bs[st][row * QPT + c4],
                       &Wt[(size_t)(n0 + row) * NDV + c * QBK + c4]);
        }
        cp_commit();
    };

    float c[2][8][4];
#pragma unroll
    for (int mt = 0; mt < 2; ++mt)
#pragma unroll
        for (int nt = 0; nt < 8; ++nt)
#pragma unroll
            for (int r = 0; r < 4; ++r) c[mt][nt][r] = 0.f;

    issue(0, 0);
    issue(1, 1);

    for (int it = 0; it < QNIT; ++it) {
        if (it == QNIT - 1) cp_wait<0>(); else cp_wait<1>();
        __syncthreads();
        int st = it & 1;
        const float* Ap = &As[st][0];
        const float* Bp = &Bs[st][0];

        // A fragments (hid): round to tf32 in-register
        unsigned a[2][2][4];
#pragma unroll
        for (int mt = 0; mt < 2; ++mt) {
            int row = wm * 32 + mt * 16 + gid;
#pragma unroll
            for (int kk = 0; kk < 2; ++kk) {
                a[mt][kk][0] = to_tf32_u(Ap[row * QPT + kk * 8 + tig]);
                a[mt][kk][1] = to_tf32_u(Ap[(row + 8) * QPT + kk * 8 + tig]);
                a[mt][kk][2] = to_tf32_u(Ap[row * QPT + kk * 8 + tig + 4]);
                a[mt][kk][3] = to_tf32_u(Ap[(row + 8) * QPT + kk * 8 + tig + 4]);
            }
        }
        // B fragments (weights, already tf32 at rest)
        unsigned bfr[8][2][2];
#pragma unroll
        for (int nt = 0; nt < 8; ++nt) {
            int row = wn * 64 + nt * 8 + gid;
#pragma unroll
            for (int kk = 0; kk < 2; ++kk) {
                bfr[nt][kk][0] = __float_as_uint(Bp[row * QPT + kk * 8 + tig]);
                bfr[nt][kk][1] = __float_as_uint(Bp[row * QPT + kk * 8 + tig + 4]);
            }
        }
#pragma unroll
        for (int mt = 0; mt < 2; ++mt)
#pragma unroll
            for (int nt = 0; nt < 8; ++nt)
#pragma unroll
                for (int kk = 0; kk < 2; ++kk)
                    mma_tf32(c[mt][nt], a[mt][kk], bfr[nt][kk][0], bfr[nt][kk][1]);

        __syncthreads();
        if (it + 2 < QNIT) issue(it + 2, st);
    }

    // Epilogue
    int b = m0 >> 11;                       // whole block in one batch
#pragma unroll
    for (int mt = 0; mt < 2; ++mt) {
        int tok  = m0 + wm * 32 + mt * 16 + gid;
        int srow = tok & (NS - 1);
#pragma unroll
        for (int nt = 0; nt < 8; ++nt) {
            int col = n0 + wn * 64 + nt * 8 + 2 * tig;   // global nout
            float g0 = gate ? gate[b * NDV + col]     : 1.f;
            float g1 = gate ? gate[b * NDV + col + 1] : 1.f;
            float b0v = bias[col], b1v = bias[col + 1];
            float v00 = to_tf32((c[mt][nt][0] + b0v) * g0);
            float v01 = to_tf32((c[mt][nt][1] + b1v) * g1);
            float v10 = to_tf32((c[mt][nt][2] + b0v) * g0);
            float v11 = to_tf32((c[mt][nt][3] + b1v) * g1);
            int h = col >> 6, d = col & 63;
            if (z == 2) {
                // V: [bh][d][s]
                float* p = out + ((size_t)(b * NH + h) * NDH + d) * NS;
                p[srow]          = v00;
                p[NS + srow]     = v01;
                p[srow + 8]      = v10;
                p[NS + srow + 8] = v11;
            } else {
                // Q/K: [bh][s][d]
                float* p = out + ((size_t)(b * NH + h) * NS) * NDH + d;
                *(float2*)&p[(size_t)srow * NDH]       = make_float2(v00, v01);
                *(float2*)&p[(size_t)(srow + 8) * NDH] = make_float2(v10, v11);
            }
        }
    }
}

// ---------------------------------------------------------------------------
// Kernel 4: flash attention with tf32 mma.sync tensor cores.  (unchanged)
// Block = 128 threads (4 warps), BQ=64 q-rows (16 per warp), BK=64.
// ---------------------------------------------------------------------------
constexpr int BQ = 64;
constexpr int BK = 64;
constexpr int NTILE = NS / BK;          // 32
constexpr int QP = 68;
constexpr int KP = 68;
constexpr int VP = 68;
constexpr int PP = 68;
constexpr int ATTN_SMEM_FLOATS =
    BQ * QP + 2 * BK * KP + 2 * NDH * VP + 4 * 16 * PP;
constexpr int ATTN_SMEM_BYTES = ATTN_SMEM_FLOATS * 4;   // 104448

__global__ void __launch_bounds__(128, 2) attn_kernel(
        const float* __restrict__ amask, float* __restrict__ out) {
    extern __shared__ float sm[];
    float* Qs = sm;                           // [BQ][QP]
    float* Ks = Qs + BQ * QP;                 // [2][BK][KP]  (token-major)
    float* Vs = Ks + 2 * BK * KP;             // [2][NDH][VP] (d-major = V^T)
    float* Ps = Vs + 2 * NDH * VP;            // [4 warps][16][PP]

    int bh = blockIdx.y;
    int b  = bh >> 4;
    int h  = bh & 15;
    int q0 = blockIdx.x * BQ;
    int tid  = threadIdx.x;
    int w    = tid >> 5;
    int lane = tid & 31;
    int gid  = lane >> 2;
    int tig  = lane & 3;

    const float* Qg = g_q + (size_t)bh * NS * NDH;
    const float* Kg = g_k + (size_t)bh * NS * NDH;
    const float* Vg = g_v + (size_t)bh * NDH * NS;   // [d][s]

    auto issue_kv = [&](int t0, int st) {
#pragma unroll
        for (int u = 0; u < 8; ++u) {
            int idx = tid + u * 128;
            int row = idx >> 4;
            int c4  = (idx & 15) * 4;
            cp_async16(&Ks[(size_t)st * BK * KP + row * KP + c4],
                       &Kg[(size_t)(t0 + row) * NDH + c4]);
            cp_async16(&Vs[(size_t)st * NDH * VP + row * VP + c4],
                       &Vg[(size_t)row * NS + t0 + c4]);
        }
        cp_commit();
    };

    issue_kv(0, 0);
    issue_kv(BK, 1);

#pragma unroll
    for (int u = 0; u < 8; ++u) {
        int idx = tid + u * 128;
        int r  = idx >> 4;
        int c4 = (idx & 15) * 4;
        *(float4*)&Qs[r * QP + c4] = *(const float4*)&Qg[(size_t)(q0 + r) * NDH + c4];
    }

    float o[8][4];
#pragma unroll
    for (int j = 0; j < 8; ++j)
#pragma unroll
        for (int r = 0; r < 4; ++r) o[j][r] = 0.f;
    float mrow[2] = {-1e30f, -1e30f};
    float lrow[2] = {0.f, 0.f};
    float* Pw = Ps + w * 16 * PP;
    int qrow = w * 16 + gid;

    for (int it = 0; it < NTILE; ++it) {
        if (it == NTILE - 1) cp_wait<0>(); else cp_wait<1>();
        __syncthreads();
        int st = it & 1;
        const float* Kp = &Ks[(size_t)st * BK * KP];
        const float* Vp = &Vs[(size_t)st * NDH * VP];
        int t0 = it * BK;

        unsigned a[8][4];
#pragma unroll
        for (int kk = 0; kk < 8; ++kk) {
            a[kk][0] = __float_as_uint(Qs[qrow * QP + kk * 8 + tig]);
            a[kk][1] = __float_as_uint(Qs[(qrow + 8) * QP + kk * 8 + tig]);
            a[kk][2] = __float_as_uint(Qs[qrow * QP + kk * 8 + tig + 4]);
            a[kk][3] = __float_as_uint(Qs[(qrow + 8) * QP + kk * 8 + tig + 4]);
        }

        float s[8][4];
#pragma unroll
        for (int nt = 0; nt < 8; ++nt) {
            s[nt][0] = s[nt][1] = s[nt][2] = s[nt][3] = 0.f;
#pragma unroll
            for (int kk = 0; kk < 8; ++kk) {
                unsigned b0 = __float_as_uint(Kp[(nt * 8 + gid) * KP + kk * 8 + tig]);
                unsigned b1 = __float_as_uint(Kp[(nt * 8 + gid) * KP + kk * 8 + tig + 4]);
                mma_tf32(s[nt], a[kk], b0, b1);
            }
        }

        float mt0 = -1e30f, mt1 = -1e30f;
#pragma unroll
        for (int nt = 0; nt < 8; ++nt) {
            float2 mk = *(const float2*)&amask[b * NS + t0 + nt * 8 + 2 * tig];
            s[nt][0] = fmaf(s[nt][0], 0.125f, mk.x);
            s[nt][1] = fmaf(s[nt][1], 0.125f, mk.y);
            s[nt][2] = fmaf(s[nt][2], 0.125f, mk.x);
            s[nt][3] = fmaf(s[nt][3], 0.125f, mk.y);
            mt0 = fmaxf(mt0, fmaxf(s[nt][0], s[nt][1]));
            mt1 = fmaxf(mt1, fmaxf(s[nt][2], s[nt][3]));
        }
        mt0 = fmaxf(mt0, __shfl_xor_sync(0xffffffffu, mt0, 1));
        mt0 = fmaxf(mt0, __shfl_xor_sync(0xffffffffu, mt0, 2));
        mt1 = fmaxf(mt1, __shfl_xor_sync(0xffffffffu, mt1, 1));
        mt1 = fmaxf(mt1, __shfl_xor_sync(0xffffffffu, mt1, 2));

        float mn0 = fmaxf(mrow[0], mt0);
        float mn1 = fmaxf(mrow[1], mt1);
        float al0 = __expf(mrow[0] - mn0);
        float al1 = __expf(mrow[1] - mn1);
        mrow[0] = mn0; mrow[1] = mn1;
        lrow[0] *= al0; lrow[1] *= al1;
#pragma unroll
        for (int j = 0; j < 8; ++j) {
            o[j][0] *= al0; o[j][1] *= al0;
            o[j][2] *= al1; o[j][3] *= al1;
        }

        float rs0 = 0.f, rs1 = 0.f;
#pragma unroll
        for (int nt = 0; nt < 8; ++nt) {
            float p0 = to_tf32(__expf(s[nt][0] - mrow[0]));
            float p1 = to_tf32(__expf(s[nt][1] - mrow[0]));
            float p2 = to_tf32(__expf(s[nt][2] - mrow[1]));
            float p3 = to_tf32(__expf(s[nt][3] - mrow[1]));
            rs0 += p0 + p1;
            rs1 += p2 + p3;
            *(float2*)&Pw[gid * PP + nt * 8 + 2 * tig]       = make_float2(p0, p1);
            *(float2*)&Pw[(gid + 8) * PP + nt * 8 + 2 * tig] = make_float2(p2, p3);
        }
        rs0 += __shfl_xor_sync(0xffffffffu, rs0, 1);
        rs0 += __shfl_xor_sync(0xffffffffu, rs0, 2);
        rs1 += __shfl_xor_sync(0xffffffffu, rs1, 1);
        rs1 += __shfl_xor_sync(0xffffffffu, rs1, 2);
        lrow[0] += rs0;
        lrow[1] += rs1;
        __syncwarp();

        unsigned pa[8][4];
#pragma unroll
        for (int kk = 0; kk < 8; ++kk) {
            pa[kk][0] = __float_as_uint(Pw[gid * PP + kk * 8 + tig]);
            pa[kk][1] = __float_as_uint(Pw[(gid + 8) * PP + kk * 8 + tig]);
            pa[kk][2] = __float_as_uint(Pw[gid * PP + kk * 8 + tig + 4]);
            pa[kk][3] = __float_as_uint(Pw[(gid + 8) * PP + kk * 8 + tig + 4]);
        }
#pragma unroll
        for (int j = 0; j < 8; ++j) {
#pragma unroll
            for (int kk = 0; kk < 8; ++kk) {
                unsigned b0 = __float_as_uint(Vp[(j * 8 + gid) * VP + kk * 8 + tig]);
                unsigned b1 = __float_as_uint(Vp[(j * 8 + gid) * VP + kk * 8 + tig + 4]);
                mma_tf32(o[j], pa[kk], b0, b1);
            }
        }

        __syncthreads();
        if (it + 2 < NTILE) issue_kv((it + 2) * BK, st);
    }

    float inv0 = 1.f / lrow[0];
    float inv1 = 1.f / lrow[1];
    int r0 = q0 + qrow;
#pragma unroll
    for (int j = 0; j < 8; ++j) {
        int col = h * NDH + j * 8 + 2 * tig;
        *(float2*)&out[((size_t)(b * NS + r0)) * NDV + col] =
            make_float2(o[j][0] * inv0, o[j][1] * inv0);
        *(float2*)&out[((size_t)(b * NS + r0 + 8)) * NDV + col] =
            make_float2(o[j][2] * inv1, o[j][3] * inv1);
    }
}

// ---------------------------------------------------------------------------
// Launch
// ---------------------------------------------------------------------------
extern "C" void kernel_launch(void* const* d_in, const int* in_sizes, int n_in,
                              void* d_out, int out_size) {
    const float* hid   = (const float*)d_in[0];
    const float* amask = (const float*)d_in[1];
    const float* txt   = (const float*)d_in[2];
    const float* tmask = (const float*)d_in[3];
    const float* Wq  = (const float*)d_in[4];
    const float* bq  = (const float*)d_in[5];
    const float* Wk  = (const float*)d_in[6];
    const float* bk  = (const float*)d_in[7];
    const float* Wv  = (const float*)d_in[8];
    const float* bv  = (const float*)d_in[9];
    const float* Wdq = (const float*)d_in[10];
    const float* bdq = (const float*)d_in[11];
    const float* Wdk = (const float*)d_in[12];
    const float* bdk = (const float*)d_in[13];
    float* out = (float*)d_out;

    cudaFuncSetAttribute(attn_kernel,
                         cudaFuncAttributeMaxDynamicSharedMemorySize,
                         ATTN_SMEM_BYTES);

    wt_kernel<<<dim3(NDV / 32, NDV / 32, 3), dim3(32, 8)>>>(Wq, Wk, Wv);
    pool_kernel<<<(NB * NDT + 255) / 256, 256>>>(txt, tmask);
    gate_kernel<<<dim3((NB * NDV + 255) / 256, 2), 256>>>(Wdq, bdq, Wdk, bdk);
    qkv_kernel<<<dim3(NDV / 128, (NB * NS) / 128, 3), 256>>>(hid, bq, bk, bv);
    attn_kernel<<<dim3(NS / BQ, NB * NH), 128, ATTN_SMEM_BYTES>>>(amask, out);
}

// round 8
// speedup vs baseline: 3.1944x; 1.1442x over previous
#include <cuda_runtime.h>
#include <cstdint>
#include <cstddef>
#include <math.h>

// Problem constants
constexpr int NB  = 4;
constexpr int NS  = 2048;
constexpr int NDV = 1024;
constexpr int NH  = 16;
constexpr int NDH = 64;
constexpr int NT  = 64;
constexpr int NDT = 768;

// Scratch (device globals: allocation-free rule)
__device__ float g_pool[NB * NDT];
__device__ float g_gate_q[NB * NDV];
__device__ float g_gate_k[NB * NDV];
__device__ float g_wt[(size_t)3 * NDV * NDV];        // [z][nout][k], tf32
__device__ float g_q[(size_t)NB * NH * NS * NDH];   // [bh][s][d]
__device__ float g_k[(size_t)NB * NH * NS * NDH];   // [bh][s][d]
__device__ float g_v[(size_t)NB * NH * NS * NDH];   // [bh][d][s]  (TRANSPOSED)

// ---------------------------------------------------------------------------
// helpers
// ---------------------------------------------------------------------------
__device__ __forceinline__ void cp_async16(void* smem_dst, const void* gmem_src) {
    unsigned int s = (unsigned int)__cvta_generic_to_shared(smem_dst);
    asm volatile("cp.async.cg.shared.global [%0], [%1], 16;\n" :: "r"(s), "l"(gmem_src));
}
__device__ __forceinline__ void cp_commit() {
    asm volatile("cp.async.commit_group;\n");
}
template <int N>
__device__ __forceinline__ void cp_wait() {
    asm volatile("cp.async.wait_group %0;\n" :: "n"(N));
}
// tf32 round (PTX cvt.rna.tf32.f32 needs a .b32 destination)
__device__ __forceinline__ float to_tf32(float x) {
    unsigned r;
    asm("cvt.rna.tf32.f32 %0, %1;" : "=r"(r) : "f"(x));
    return __uint_as_float(r);
}
__device__ __forceinline__ unsigned to_tf32_u(float x) {
    unsigned r;
    asm("cvt.rna.tf32.f32 %0, %1;" : "=r"(r) : "f"(x));
    return r;
}
// D += A*B, m16n8k8 tf32
__device__ __forceinline__ void mma_tf32(float* c, const unsigned* a,
                                         unsigned b0, unsigned b1) {
    asm volatile(
        "mma.sync.aligned.m16n8k8.row.col.f32.tf32.tf32.f32 "
        "{%0,%1,%2,%3}, {%4,%5,%6,%7}, {%8,%9}, {%0,%1,%2,%3};\n"
        : "+f"(c[0]), "+f"(c[1]), "+f"(c[2]), "+f"(c[3])
        : "r"(a[0]), "r"(a[1]), "r"(a[2]), "r"(a[3]), "r"(b0), "r"(b1));
}
// ldmatrix x4 (b16 view; addr is per-lane shared-space address)
__device__ __forceinline__ void ldsm_x4(unsigned* r, const void* p) {
    unsigned addr = (unsigned)__cvta_generic_to_shared(p);
    asm volatile("ldmatrix.sync.aligned.m8n8.x4.shared.b16 {%0,%1,%2,%3}, [%4];"
                 : "=r"(r[0]), "=r"(r[1]), "=r"(r[2]), "=r"(r[3]) : "r"(addr));
}

// ---------------------------------------------------------------------------
// Kernel 0: weight transpose  g_wt[z][n][k] = to_tf32(W_z[k][n])
// ---------------------------------------------------------------------------
__global__ void wt_kernel(const float* __restrict__ Wq,
                          const float* __restrict__ Wk,
                          const float* __restrict__ Wv) {
    __shared__ float t[32][33];
    int z = blockIdx.z;
    const float* W = (z == 0) ? Wq : (z == 1) ? Wk : Wv;
    float* out = g_wt + (size_t)z * NDV * NDV;
    int k0 = blockIdx.x * 32, n0 = blockIdx.y * 32;
    int x = threadIdx.x, y = threadIdx.y;       // 32 x 8
#pragma unroll
    for (int i = 0; i < 32; i += 8)
        t[y + i][x] = W[(size_t)(k0 + y + i) * NDV + n0 + x];
    __syncthreads();
#pragma unroll
    for (int i = 0; i < 32; i += 8)
        out[(size_t)(n0 + y + i) * NDV + k0 + x] = to_tf32(t[x][y + i]);
}

// ---------------------------------------------------------------------------
// Kernel 1: masked-mean pool over text tokens.  pool[b,d]
// ---------------------------------------------------------------------------
__global__ void pool_kernel(const float* __restrict__ txt,
                            const float* __restrict__ tmask) {
    int i = blockIdx.x * blockDim.x + threadIdx.x;
    if (i >= NB * NDT) return;
    int b = i / NDT;
    int d = i - b * NDT;
    float s = 0.f, ms = 0.f;
#pragma unroll 4
    for (int t = 0; t < NT; ++t) {
        float mv = tmask[b * NT + t];
        s += txt[((size_t)(b * NT + t)) * NDT + d] * mv;
        ms += mv;
    }
    g_pool[i] = s / ms;
}

// ---------------------------------------------------------------------------
// Kernel 2: gates = 1 + sigmoid(pool @ Wd + bd).  blockIdx.y: 0 = q, 1 = k
// ---------------------------------------------------------------------------
__global__ void gate_kernel(const float* __restrict__ Wdq,
                            const float* __restrict__ bdq,
                            const float* __restrict__ Wdk,
                            const float* __restrict__ bdk) {
    int idx = blockIdx.x * blockDim.x + threadIdx.x;
    if (idx >= NB * NDV) return;
    int which = blockIdx.y;
    int b = idx / NDV;
    int n = idx - b * NDV;
    const float* W  = which ? Wdk : Wdq;
    const float* bb = which ? bdk : bdq;
    float acc = bb[n];
    const float* p = &g_pool[b * NDT];
#pragma unroll 4
    for (int d = 0; d < NDT; ++d)
        acc += p[d] * W[(size_t)d * NDV + n];
    float gate = 1.f + 1.f / (1.f + expf(-acc));
    if (which) g_gate_k[idx] = gate;
    else       g_gate_q[idx] = gate;
}

// ---------------------------------------------------------------------------
// Kernel 3: QKV projection via tf32 mma.sync + ldmatrix fragments.
// ---------------------------------------------------------------------------
constexpr int QBK = 16;
constexpr int QPT = 20;                     // smem pitch (20 = 4 mod 32 banks)
constexpr int QNIT = NDV / QBK;             // 64

__global__ void __launch_bounds__(256) qkv_kernel(
        const float* __restrict__ hid,
        const float* __restrict__ bq,
        const float* __restrict__ bk,
        const float* __restrict__ bv) {
    __shared__ float As[2][128 * QPT];      // hid tile  [token][k]
    __shared__ float Bs[2][128 * QPT];      // Wt tile   [nout][k]

    int z = blockIdx.z;
    const float* Wt = g_wt + (size_t)z * NDV * NDV;
    const float* bias = (z == 0) ? bq : (z == 1) ? bk : bv;
    const float* gate = (z == 0) ? g_gate_q : (z == 1) ? g_gate_k : nullptr;
    float* out = (z == 0) ? g_q : (z == 1) ? g_k : g_v;

    int m0 = blockIdx.y * 128;              // token base
    int n0 = blockIdx.x * 128;              // nout base
    int tid  = threadIdx.x;
    int warp = tid >> 5;
    int lane = tid & 31;
    int gid  = lane >> 2;
    int tig  = lane & 3;
    int wm = warp & 3;                      // 0..3 (token)
    int wn = warp >> 2;                     // 0..1 (nout)
    // ldmatrix per-lane row/col selectors
    int l16 = lane & 15;                    // row within 16-row A tile
    int ah  = (lane >> 4) * 4;              // col half for A x4 (0 or 4)
    int l8  = lane & 7;                     // row within 8-row B tile
    int bh4 = ((lane >> 3) & 3) * 4;        // col quarter for B x4 (0,4,8,12)

    auto issue = [&](int c, int st) {
#pragma unroll
        for (int u = 0; u < 2; ++u) {
            int idx = tid * 2 + u;
            int row = idx >> 2;
            int c4  = (idx & 3) * 4;
            cp_async16(&As[st][row * QPT + c4],
                       &hid[(size_t)(m0 + row) * NDV + c * QBK + c4]);
            cp_async16(&Bs[st][row * QPT + c4],
                       &Wt[(size_t)(n0 + row) * NDV + c * QBK + c4]);
        }
        cp_commit();
    };

    float c[2][8][4];
#pragma unroll
    for (int mt = 0; mt < 2; ++mt)
#pragma unroll
        for (int nt = 0; nt < 8; ++nt)
#pragma unroll
            for (int r = 0; r < 4; ++r) c[mt][nt][r] = 0.f;

    issue(0, 0);
    issue(1, 1);

    for (int it = 0; it < QNIT; ++it) {
        if (it == QNIT - 1) cp_wait<0>(); else cp_wait<1>();
        __syncthreads();
        int st = it & 1;
        const float* Ap = &As[st][0];
        const float* Bp = &Bs[st][0];

        // A fragments via ldmatrix, then tf32-round in-register
        unsigned a[2][2][4];
#pragma unroll
        for (int mt = 0; mt < 2; ++mt) {
#pragma unroll
            for (int kk = 0; kk < 2; ++kk) {
                ldsm_x4(a[mt][kk],
                        &Ap[(wm * 32 + mt * 16 + l16) * QPT + kk * 8 + ah]);
#pragma unroll
                for (int r = 0; r < 4; ++r)
                    a[mt][kk][r] = to_tf32_u(__uint_as_float(a[mt][kk][r]));
            }
        }
        // B fragments via ldmatrix (one x4 covers both k-chunks)
        unsigned bfr[8][4];
#pragma unroll
        for (int nt = 0; nt < 8; ++nt)
            ldsm_x4(bfr[nt], &Bp[(wn * 64 + nt * 8 + l8) * QPT + bh4]);

#pragma unroll
        for (int mt = 0; mt < 2; ++mt)
#pragma unroll
            for (int nt = 0; nt < 8; ++nt) {
                mma_tf32(c[mt][nt], a[mt][0], bfr[nt][0], bfr[nt][1]);
                mma_tf32(c[mt][nt], a[mt][1], bfr[nt][2], bfr[nt][3]);
            }

        __syncthreads();
        if (it + 2 < QNIT) issue(it + 2, st);
    }

    // Epilogue
    int b = m0 >> 11;
#pragma unroll
    for (int mt = 0; mt < 2; ++mt) {
        int tok  = m0 + wm * 32 + mt * 16 + gid;
        int srow = tok & (NS - 1);
#pragma unroll
        for (int nt = 0; nt < 8; ++nt) {
            int col = n0 + wn * 64 + nt * 8 + 2 * tig;
            float g0 = gate ? gate[b * NDV + col]     : 1.f;
            float g1 = gate ? gate[b * NDV + col + 1] : 1.f;
            float b0v = bias[col], b1v = bias[col + 1];
            float v00 = to_tf32((c[mt][nt][0] + b0v) * g0);
            float v01 = to_tf32((c[mt][nt][1] + b1v) * g1);
            float v10 = to_tf32((c[mt][nt][2] + b0v) * g0);
            float v11 = to_tf32((c[mt][nt][3] + b1v) * g1);
            int h = col >> 6, d = col & 63;
            if (z == 2) {
                float* p = out + ((size_t)(b * NH + h) * NDH + d) * NS;
                p[srow]          = v00;
                p[NS + srow]     = v01;
                p[srow + 8]      = v10;
                p[NS + srow + 8] = v11;
            } else {
                float* p = out + ((size_t)(b * NH + h) * NS) * NDH + d;
                *(float2*)&p[(size_t)srow * NDH]       = make_float2(v00, v01);
                *(float2*)&p[(size_t)(srow + 8) * NDH] = make_float2(v10, v11);
            }
        }
    }
}

// ---------------------------------------------------------------------------
// Kernel 4: flash attention, tf32 mma.sync + ldmatrix fragments.
// Block = 128 threads (4 warps), BQ=64, BK=64, double-buffered cp.async.
// ---------------------------------------------------------------------------
constexpr int BQ = 64;
constexpr int BK = 64;
constexpr int NTILE = NS / BK;          // 32
constexpr int QP = 68;
constexpr int KP = 68;
constexpr int VP = 68;
constexpr int PP = 68;
constexpr int ATTN_SMEM_FLOATS =
    BQ * QP + 2 * BK * KP + 2 * NDH * VP + 4 * 16 * PP;
constexpr int ATTN_SMEM_BYTES = ATTN_SMEM_FLOATS * 4;   // 104448

__global__ void __launch_bounds__(128, 2) attn_kernel(
        const float* __restrict__ amask, float* __restrict__ out) {
    extern __shared__ float sm[];
    float* Qs = sm;                           // [BQ][QP]
    float* Ks = Qs + BQ * QP;                 // [2][BK][KP]  (token-major)
    float* Vs = Ks + 2 * BK * KP;             // [2][NDH][VP] (d-major = V^T)
    float* Ps = Vs + 2 * NDH * VP;            // [4 warps][16][PP]

    int bh = blockIdx.y;
    int b  = bh >> 4;
    int h  = bh & 15;
    int q0 = blockIdx.x * BQ;
    int tid  = threadIdx.x;
    int w    = tid >> 5;
    int lane = tid & 31;
    int gid  = lane >> 2;
    int tig  = lane & 3;
    int l16 = lane & 15;
    int ah  = (lane >> 4) * 4;
    int l8  = lane & 7;
    int bh4 = ((lane >> 3) & 3) * 4;

    const float* Qg = g_q + (size_t)bh * NS * NDH;
    const float* Kg = g_k + (size_t)bh * NS * NDH;
    const float* Vg = g_v + (size_t)bh * NDH * NS;   // [d][s]

    auto issue_kv = [&](int t0, int st) {
#pragma unroll
        for (int u = 0; u < 8; ++u) {
            int idx = tid + u * 128;
            int row = idx >> 4;
            int c4  = (idx & 15) * 4;
            cp_async16(&Ks[(size_t)st * BK * KP + row * KP + c4],
                       &Kg[(size_t)(t0 + row) * NDH + c4]);
            cp_async16(&Vs[(size_t)st * NDH * VP + row * VP + c4],
                       &Vg[(size_t)row * NS + t0 + c4]);
        }
        cp_commit();
    };

    issue_kv(0, 0);
    issue_kv(BK, 1);

#pragma unroll
    for (int u = 0; u < 8; ++u) {
        int idx = tid + u * 128;
        int r  = idx >> 4;
        int c4 = (idx & 15) * 4;
        *(float4*)&Qs[r * QP + c4] = *(const float4*)&Qg[(size_t)(q0 + r) * NDH + c4];
    }
    __syncthreads();

    // Q A-fragments: invariant across k-tiles — load once via ldmatrix
    unsigned a[8][4];
#pragma unroll
    for (int kk = 0; kk < 8; ++kk)
        ldsm_x4(a[kk], &Qs[(w * 16 + l16) * QP + kk * 8 + ah]);

    float o[8][4];
#pragma unroll
    for (int j = 0; j < 8; ++j)
#pragma unroll
        for (int r = 0; r < 4; ++r) o[j][r] = 0.f;
    float mrow[2] = {-1e30f, -1e30f};
    float lrow[2] = {0.f, 0.f};
    float* Pw = Ps + w * 16 * PP;

    for (int it = 0; it < NTILE; ++it) {
        if (it == NTILE - 1) cp_wait<0>(); else cp_wait<1>();
        __syncthreads();
        int st = it & 1;
        const float* Kp = &Ks[(size_t)st * BK * KP];
        const float* Vp = &Vs[(size_t)st * NDH * VP];
        int t0 = it * BK;

        // S = Q @ K^T : K B-fragments via ldmatrix (x4 covers k16)
        float s[8][4];
#pragma unroll
        for (int nt = 0; nt < 8; ++nt) {
            s[nt][0] = s[nt][1] = s[nt][2] = s[nt][3] = 0.f;
#pragma unroll
            for (int kp = 0; kp < 4; ++kp) {
                unsigned bf[4];
                ldsm_x4(bf, &Kp[(nt * 8 + l8) * KP + kp * 16 + bh4]);
                mma_tf32(s[nt], a[2 * kp],     bf[0], bf[1]);
                mma_tf32(s[nt], a[2 * kp + 1], bf[2], bf[3]);
            }
        }

        float mt0 = -1e30f, mt1 = -1e30f;
#pragma unroll
        for (int nt = 0; nt < 8; ++nt) {
            float2 mk = *(const float2*)&amask[b * NS + t0 + nt * 8 + 2 * tig];
            s[nt][0] = fmaf(s[nt][0], 0.125f, mk.x);
            s[nt][1] = fmaf(s[nt][1], 0.125f, mk.y);
            s[nt][2] = fmaf(s[nt][2], 0.125f, mk.x);
            s[nt][3] = fmaf(s[nt][3], 0.125f, mk.y);
            mt0 = fmaxf(mt0, fmaxf(s[nt][0], s[nt][1]));
            mt1 = fmaxf(mt1, fmaxf(s[nt][2], s[nt][3]));
        }
        mt0 = fmaxf(mt0, __shfl_xor_sync(0xffffffffu, mt0, 1));
        mt0 = fmaxf(mt0, __shfl_xor_sync(0xffffffffu, mt0, 2));
        mt1 = fmaxf(mt1, __shfl_xor_sync(0xffffffffu, mt1, 1));
        mt1 = fmaxf(mt1, __shfl_xor_sync(0xffffffffu, mt1, 2));

        float mn0 = fmaxf(mrow[0], mt0);
        float mn1 = fmaxf(mrow[1], mt1);
        float al0 = __expf(mrow[0] - mn0);
        float al1 = __expf(mrow[1] - mn1);
        mrow[0] = mn0; mrow[1] = mn1;
        lrow[0] *= al0; lrow[1] *= al1;
#pragma unroll
        for (int j = 0; j < 8; ++j) {
            o[j][0] *= al0; o[j][1] *= al0;
            o[j][2] *= al1; o[j][3] *= al1;
        }

        float rs0 = 0.f, rs1 = 0.f;
#pragma unroll
        for (int nt = 0; nt < 8; ++nt) {
            float p0 = to_tf32(__expf(s[nt][0] - mrow[0]));
            float p1 = to_tf32(__expf(s[nt][1] - mrow[0]));
            float p2 = to_tf32(__expf(s[nt][2] - mrow[1]));
            float p3 = to_tf32(__expf(s[nt][3] - mrow[1]));
            rs0 += p0 + p1;
            rs1 += p2 + p3;
            *(float2*)&Pw[gid * PP + nt * 8 + 2 * tig]       = make_float2(p0, p1);
            *(float2*)&Pw[(gid + 8) * PP + nt * 8 + 2 * tig] = make_float2(p2, p3);
        }
        rs0 += __shfl_xor_sync(0xffffffffu, rs0, 1);
        rs0 += __shfl_xor_sync(0xffffffffu, rs0, 2);
        rs1 += __shfl_xor_sync(0xffffffffu, rs1, 1);
        rs1 += __shfl_xor_sync(0xffffffffu, rs1, 2);
        lrow[0] += rs0;
        lrow[1] += rs1;
        __syncwarp();

        // P A-fragments via ldmatrix
        unsigned pa[8][4];
#pragma unroll
        for (int kk = 0; kk < 8; ++kk)
            ldsm_x4(pa[kk], &Pw[l16 * PP + kk * 8 + ah]);

        // O += P @ V : V B-fragments via ldmatrix
#pragma unroll
        for (int j = 0; j < 8; ++j) {
#pragma unroll
            for (int kp = 0; kp < 4; ++kp) {
                unsigned bf[4];
                ldsm_x4(bf, &Vp[(j * 8 + l8) * VP + kp * 16 + bh4]);
                mma_tf32(o[j], pa[2 * kp],     bf[0], bf[1]);
                mma_tf32(o[j], pa[2 * kp + 1], bf[2], bf[3]);
            }
        }

        __syncthreads();
        if (it + 2 < NTILE) issue_kv((it + 2) * BK, st);
    }

    float inv0 = 1.f / lrow[0];
    float inv1 = 1.f / lrow[1];
    int r0 = q0 + w * 16 + gid;
#pragma unroll
    for (int j = 0; j < 8; ++j) {
        int col = h * NDH + j * 8 + 2 * tig;
        *(float2*)&out[((size_t)(b * NS + r0)) * NDV + col] =
            make_float2(o[j][0] * inv0, o[j][1] * inv0);
        *(float2*)&out[((size_t)(b * NS + r0 + 8)) * NDV + col] =
            make_float2(o[j][2] * inv1, o[j][3] * inv1);
    }
}

// ---------------------------------------------------------------------------
// Launch
// ---------------------------------------------------------------------------
extern "C" void kernel_launch(void* const* d_in, const int* in_sizes, int n_in,
                              void* d_out, int out_size) {
    const float* hid   = (const float*)d_in[0];
    const float* amask = (const float*)d_in[1];
    const float* txt   = (const float*)d_in[2];
    const float* tmask = (const float*)d_in[3];
    const float* Wq  = (const float*)d_in[4];
    const float* bq  = (const float*)d_in[5];
    const float* Wk  = (const float*)d_in[6];
    const float* bk  = (const float*)d_in[7];
    const float* Wv  = (const float*)d_in[8];
    const float* bv  = (const float*)d_in[9];
    const float* Wdq = (const float*)d_in[10];
    const float* bdq = (const float*)d_in[11];
    const float* Wdk = (const float*)d_in[12];
    const float* bdk = (const float*)d_in[13];
    float* out = (float*)d_out;

    cudaFuncSetAttribute(attn_kernel,
                         cudaFuncAttributeMaxDynamicSharedMemorySize,
                         ATTN_SMEM_BYTES);

    wt_kernel<<<dim3(NDV / 32, NDV / 32, 3), dim3(32, 8)>>>(Wq, Wk, Wv);
    pool_kernel<<<(NB * NDT + 255) / 256, 256>>>(txt, tmask);
    gate_kernel<<<dim3((NB * NDV + 255) / 256, 2), 256>>>(Wdq, bdq, Wdk, bdk);
    qkv_kernel<<<dim3(NDV / 128, (NB * NS) / 128, 3), 256>>>(hid, bq, bk, bv);
    attn_kernel<<<dim3(NS / BQ, NB * NH), 128, ATTN_SMEM_BYTES>>>(amask, out);
}

// round 10
// speedup vs baseline: 3.2067x; 1.0039x over previous
#include <cuda_runtime.h>
#include <cstdint>
#include <cstddef>
#include <math.h>

// Problem constants
constexpr int NB  = 4;
constexpr int NS  = 2048;
constexpr int NDV = 1024;
constexpr int NH  = 16;
constexpr int NDH = 64;
constexpr int NT  = 64;
constexpr int NDT = 768;

// Scratch (device globals: allocation-free rule)
__device__ float g_pool[NB * NDT];
__device__ float g_gate_q[NB * NDV];
__device__ float g_gate_k[NB * NDV];
__device__ float g_wt[(size_t)3 * NDV * NDV];        // [z][nout][k], tf32
__device__ float g_q[(size_t)NB * NH * NS * NDH];   // [bh][s][d]
__device__ float g_k[(size_t)NB * NH * NS * NDH];   // [bh][s][d]
__device__ float g_v[(size_t)NB * NH * NS * NDH];   // [bh][d][s]  (TRANSPOSED)

// ---------------------------------------------------------------------------
// helpers
// ---------------------------------------------------------------------------
__device__ __forceinline__ void cp_async16(void* smem_dst, const void* gmem_src) {
    unsigned int s = (unsigned int)__cvta_generic_to_shared(smem_dst);
    asm volatile("cp.async.cg.shared.global [%0], [%1], 16;\n" :: "r"(s), "l"(gmem_src));
}
__device__ __forceinline__ void cp_commit() {
    asm volatile("cp.async.commit_group;\n");
}
template <int N>
__device__ __forceinline__ void cp_wait() {
    asm volatile("cp.async.wait_group %0;\n" :: "n"(N));
}
// tf32 round (PTX cvt.rna.tf32.f32 needs a .b32 destination)
__device__ __forceinline__ float to_tf32(float x) {
    unsigned r;
    asm("cvt.rna.tf32.f32 %0, %1;" : "=r"(r) : "f"(x));
    return __uint_as_float(r);
}
__device__ __forceinline__ unsigned to_tf32_u(float x) {
    unsigned r;
    asm("cvt.rna.tf32.f32 %0, %1;" : "=r"(r) : "f"(x));
    return r;
}
// D += A*B, m16n8k8 tf32
__device__ __forceinline__ void mma_tf32(float* c, const unsigned* a,
                                         unsigned b0, unsigned b1) {
    asm volatile(
        "mma.sync.aligned.m16n8k8.row.col.f32.tf32.tf32.f32 "
        "{%0,%1,%2,%3}, {%4,%5,%6,%7}, {%8,%9}, {%0,%1,%2,%3};\n"
        : "+f"(c[0]), "+f"(c[1]), "+f"(c[2]), "+f"(c[3])
        : "r"(a[0]), "r"(a[1]), "r"(a[2]), "r"(a[3]), "r"(b0), "r"(b1));
}
// ldmatrix x4 (b16 view; addr is per-lane shared-space address)
__device__ __forceinline__ void ldsm_x4(unsigned* r, const void* p) {
    unsigned addr = (unsigned)__cvta_generic_to_shared(p);
    asm volatile("ldmatrix.sync.aligned.m8n8.x4.shared.b16 {%0,%1,%2,%3}, [%4];"
                 : "=r"(r[0]), "=r"(r[1]), "=r"(r[2]), "=r"(r[3]) : "r"(addr));
}

// ---------------------------------------------------------------------------
// Kernel 0: weight transpose  g_wt[z][n][k] = to_tf32(W_z[k][n])
// ---------------------------------------------------------------------------
__global__ void wt_kernel(const float* __restrict__ Wq,
                          const float* __restrict__ Wk,
                          const float* __restrict__ Wv) {
    __shared__ float t[32][33];
    int z = blockIdx.z;
    const float* W = (z == 0) ? Wq : (z == 1) ? Wk : Wv;
    float* out = g_wt + (size_t)z * NDV * NDV;
    int k0 = blockIdx.x * 32, n0 = blockIdx.y * 32;
    int x = threadIdx.x, y = threadIdx.y;       // 32 x 8
#pragma unroll
    for (int i = 0; i < 32; i += 8)
        t[y + i][x] = W[(size_t)(k0 + y + i) * NDV + n0 + x];
    __syncthreads();
#pragma unroll
    for (int i = 0; i < 32; i += 8)
        out[(size_t)(n0 + y + i) * NDV + k0 + x] = to_tf32(t[x][y + i]);
}

// ---------------------------------------------------------------------------
// Kernel 1: masked-mean pool over text tokens.  pool[b,d]
// ---------------------------------------------------------------------------
__global__ void pool_kernel(const float* __restrict__ txt,
                            const float* __restrict__ tmask) {
    int i = blockIdx.x * blockDim.x + threadIdx.x;
    if (i >= NB * NDT) return;
    int b = i / NDT;
    int d = i - b * NDT;
    float s = 0.f, ms = 0.f;
#pragma unroll 4
    for (int t = 0; t < NT; ++t) {
        float mv = tmask[b * NT + t];
        s += txt[((size_t)(b * NT + t)) * NDT + d] * mv;
        ms += mv;
    }
    g_pool[i] = s / ms;
}

// ---------------------------------------------------------------------------
// Kernel 2: gates = 1 + sigmoid(pool @ Wd + bd).  blockIdx.y: 0 = q, 1 = k
// ---------------------------------------------------------------------------
__global__ void gate_kernel(const float* __restrict__ Wdq,
                            const float* __restrict__ bdq,
                            const float* __restrict__ Wdk,
                            const float* __restrict__ bdk) {
    int idx = blockIdx.x * blockDim.x + threadIdx.x;
    if (idx >= NB * NDV) return;
    int which = blockIdx.y;
    int b = idx / NDV;
    int n = idx - b * NDV;
    const float* W  = which ? Wdk : Wdq;
    const float* bb = which ? bdk : bdq;
    float acc = bb[n];
    const float* p = &g_pool[b * NDT];
#pragma unroll 4
    for (int d = 0; d < NDT; ++d)
        acc += p[d] * W[(size_t)d * NDV + n];
    float gate = 1.f + 1.f / (1.f + expf(-acc));
    if (which) g_gate_k[idx] = gate;
    else       g_gate_q[idx] = gate;
}

// ---------------------------------------------------------------------------
// Kernel 3: QKV projection, tf32 mma.sync + ldmatrix.
// 3-stage cp.async pipeline (DYNAMIC smem, 61440 B), ONE barrier per iter.
// ---------------------------------------------------------------------------
constexpr int QBK = 16;
constexpr int QPT = 20;                     // smem pitch (20 = 4 mod 32 banks)
constexpr int QNIT = NDV / QBK;             // 64
constexpr int QSTG = 3;
constexpr int QTILE = 128 * QPT;            // floats per tile
constexpr int QKV_SMEM_BYTES = QSTG * 2 * QTILE * 4;   // 61440

__global__ void __launch_bounds__(256, 2) qkv_kernel(
        const float* __restrict__ hid,
        const float* __restrict__ bq,
        const float* __restrict__ bk,
        const float* __restrict__ bv) {
    extern __shared__ float qsm[];
    float* As = qsm;                         // [QSTG][QTILE] hid tile [token][k]
    float* Bs = qsm + QSTG * QTILE;          // [QSTG][QTILE] Wt tile  [nout][k]

    int z = blockIdx.z;
    const float* Wt = g_wt + (size_t)z * NDV * NDV;
    const float* bias = (z == 0) ? bq : (z == 1) ? bk : bv;
    const float* gate = (z == 0) ? g_gate_q : (z == 1) ? g_gate_k : nullptr;
    float* out = (z == 0) ? g_q : (z == 1) ? g_k : g_v;

    int m0 = blockIdx.y * 128;              // token base
    int n0 = blockIdx.x * 128;              // nout base
    int tid  = threadIdx.x;
    int warp = tid >> 5;
    int lane = tid & 31;
    int gid  = lane >> 2;
    int tig  = lane & 3;
    int wm = warp & 3;                      // 0..3 (token)
    int wn = warp >> 2;                     // 0..1 (nout)
    int l16 = lane & 15;
    int ah  = (lane >> 4) * 4;
    int l8  = lane & 7;
    int bh4 = ((lane >> 3) & 3) * 4;

    auto issue = [&](int c, int st) {
#pragma unroll
        for (int u = 0; u < 2; ++u) {
            int idx = tid * 2 + u;
            int row = idx >> 2;
            int c4  = (idx & 3) * 4;
            cp_async16(&As[st * QTILE + row * QPT + c4],
                       &hid[(size_t)(m0 + row) * NDV + c * QBK + c4]);
            cp_async16(&Bs[st * QTILE + row * QPT + c4],
                       &Wt[(size_t)(n0 + row) * NDV + c * QBK + c4]);
        }
        cp_commit();
    };

    float c[2][8][4];
#pragma unroll
    for (int mt = 0; mt < 2; ++mt)
#pragma unroll
        for (int nt = 0; nt < 8; ++nt)
#pragma unroll
            for (int r = 0; r < 4; ++r) c[mt][nt][r] = 0.f;

    issue(0, 0);
    issue(1, 1);

    int st = 0;
    for (int it = 0; it < QNIT; ++it) {
        cp_wait<1>();                       // tile it resident
        __syncthreads();                    // all warps done with stage (it-1)%3
        int st2 = st + 2; if (st2 >= QSTG) st2 -= QSTG;
        if (it + 2 < QNIT) issue(it + 2, st2);

        const float* Ap = &As[st * QTILE];
        const float* Bp = &Bs[st * QTILE];

        unsigned a[2][2][4];
#pragma unroll
        for (int mt = 0; mt < 2; ++mt) {
#pragma unroll
            for (int kk = 0; kk < 2; ++kk) {
                ldsm_x4(a[mt][kk],
                        &Ap[(wm * 32 + mt * 16 + l16) * QPT + kk * 8 + ah]);
#pragma unroll
                for (int r = 0; r < 4; ++r)
                    a[mt][kk][r] = to_tf32_u(__uint_as_float(a[mt][kk][r]));
            }
        }
        unsigned bfr[8][4];
#pragma unroll
        for (int nt = 0; nt < 8; ++nt)
            ldsm_x4(bfr[nt], &Bp[(wn * 64 + nt * 8 + l8) * QPT + bh4]);

#pragma unroll
        for (int mt = 0; mt < 2; ++mt)
#pragma unroll
            for (int nt = 0; nt < 8; ++nt) {
                mma_tf32(c[mt][nt], a[mt][0], bfr[nt][0], bfr[nt][1]);
                mma_tf32(c[mt][nt], a[mt][1], bfr[nt][2], bfr[nt][3]);
            }

        if (++st == QSTG) st = 0;
    }

    // Epilogue
    int b = m0 >> 11;
#pragma unroll
    for (int mt = 0; mt < 2; ++mt) {
        int tok  = m0 + wm * 32 + mt * 16 + gid;
        int srow = tok & (NS - 1);
#pragma unroll
        for (int nt = 0; nt < 8; ++nt) {
            int col = n0 + wn * 64 + nt * 8 + 2 * tig;
            float g0 = gate ? gate[b * NDV + col]     : 1.f;
            float g1 = gate ? gate[b * NDV + col + 1] : 1.f;
            float b0v = bias[col], b1v = bias[col + 1];
            float v00 = to_tf32((c[mt][nt][0] + b0v) * g0);
            float v01 = to_tf32((c[mt][nt][1] + b1v) * g1);
            float v10 = to_tf32((c[mt][nt][2] + b0v) * g0);
            float v11 = to_tf32((c[mt][nt][3] + b1v) * g1);
            int h = col >> 6, d = col & 63;
            if (z == 2) {
                float* p = out + ((size_t)(b * NH + h) * NDH + d) * NS;
                p[srow]          = v00;
                p[NS + srow]     = v01;
                p[srow + 8]      = v10;
                p[NS + srow + 8] = v11;
            } else {
                float* p = out + ((size_t)(b * NH + h) * NS) * NDH + d;
                *(float2*)&p[(size_t)srow * NDH]       = make_float2(v00, v01);
                *(float2*)&p[(size_t)(srow + 8) * NDH] = make_float2(v10, v11);
            }
        }
    }
}

// ---------------------------------------------------------------------------
// Kernel 4: flash attention, tf32 mma.sync.
// No Qs (Q frags gathered from gmem once); no Ps (C->A frag relayout via
// quad shuffles).  smem = 2-stage K/V only (69.6 KB) -> 3 blocks/SM.
// ONE barrier per iteration (issue-at-top).
// ---------------------------------------------------------------------------
constexpr int BQ = 64;
constexpr int BK = 64;
constexpr int NTILE = NS / BK;          // 32
constexpr int KP = 68;
constexpr int VP = 68;
constexpr int ATTN_SMEM_FLOATS = 2 * BK * KP + 2 * NDH * VP;
constexpr int ATTN_SMEM_BYTES = ATTN_SMEM_FLOATS * 4;   // 69632

__global__ void __launch_bounds__(128, 3) attn_kernel(
        const float* __restrict__ amask, float* __restrict__ out) {
    extern __shared__ float sm[];
    float* Ks = sm;                           // [2][BK][KP]  (token-major)
    float* Vs = Ks + 2 * BK * KP;             // [2][NDH][VP] (d-major = V^T)

    int bh = blockIdx.y;
    int b  = bh >> 4;
    int h  = bh & 15;
    int q0 = blockIdx.x * BQ;
    int tid  = threadIdx.x;
    int w    = tid >> 5;
    int lane = tid & 31;
    int gid  = lane >> 2;
    int tig  = lane & 3;
    int l8  = lane & 7;
    int bh4 = ((lane >> 3) & 3) * 4;
    int srcl = (lane & ~3) | (tig >> 1);      // quad-local source for P relayout

    const float* Qg = g_q + (size_t)bh * NS * NDH;
    const float* Kg = g_k + (size_t)bh * NS * NDH;
    const float* Vg = g_v + (size_t)bh * NDH * NS;   // [d][s]

    auto issue_kv = [&](int t0, int st) {
#pragma unroll
        for (int u = 0; u < 8; ++u) {
            int idx = tid + u * 128;
            int row = idx >> 4;
            int c4  = (idx & 15) * 4;
            cp_async16(&Ks[(size_t)st * BK * KP + row * KP + c4],
                       &Kg[(size_t)(t0 + row) * NDH + c4]);
            cp_async16(&Vs[(size_t)st * NDH * VP + row * VP + c4],
                       &Vg[(size_t)row * NS + t0 + c4]);
        }
        cp_commit();
    };

    issue_kv(0, 0);

    // Q A-fragments straight from gmem (g_q is tf32 at rest), once.
    unsigned a[8][4];
    {
        const float* Qr0 = Qg + (size_t)(q0 + w * 16 + gid) * NDH;
        const float* Qr8 = Qr0 + 8 * NDH;
#pragma unroll
        for (int kk = 0; kk < 8; ++kk) {
            a[kk][0] = __float_as_uint(Qr0[kk * 8 + tig]);
            a[kk][1] = __float_as_uint(Qr8[kk * 8 + tig]);
            a[kk][2] = __float_as_uint(Qr0[kk * 8 + tig + 4]);
            a[kk][3] = __float_as_uint(Qr8[kk * 8 + tig + 4]);
        }
    }

    float o[8][4];
#pragma unroll
    for (int j = 0; j < 8; ++j)
#pragma unroll
        for (int r = 0; r < 4; ++r) o[j][r] = 0.f;
    float mrow[2] = {-1e30f, -1e30f};
    float lrow[2] = {0.f, 0.f};

    for (int it = 0; it < NTILE; ++it) {
        cp_wait<0>();                        // tile it resident
        __syncthreads();                     // all warps done with stage (it-1)&1
        if (it + 1 < NTILE) issue_kv((it + 1) * BK, (it + 1) & 1);
        int st = it & 1;
        const float* Kp = &Ks[(size_t)st * BK * KP];
        const float* Vp = &Vs[(size_t)st * NDH * VP];
        int t0 = it * BK;

        // S = Q @ K^T : K B-fragments via ldmatrix
        float s[8][4];
#pragma unroll
        for (int nt = 0; nt < 8; ++nt) {
            s[nt][0] = s[nt][1] = s[nt][2] = s[nt][3] = 0.f;
#pragma unroll
            for (int kp = 0; kp < 4; ++kp) {
                unsigned bf[4];
                ldsm_x4(bf, &Kp[(nt * 8 + l8) * KP + kp * 16 + bh4]);
                mma_tf32(s[nt], a[2 * kp],     bf[0], bf[1]);
                mma_tf32(s[nt], a[2 * kp + 1], bf[2], bf[3]);
            }
        }

        float mt0 = -1e30f, mt1 = -1e30f;
#pragma unroll
        for (int nt = 0; nt < 8; ++nt) {
            float2 mk = *(const float2*)&amask[b * NS + t0 + nt * 8 + 2 * tig];
            s[nt][0] = fmaf(s[nt][0], 0.125f, mk.x);
            s[nt][1] = fmaf(s[nt][1], 0.125f, mk.y);
            s[nt][2] = fmaf(s[nt][2], 0.125f, mk.x);
            s[nt][3] = fmaf(s[nt][3], 0.125f, mk.y);
            mt0 = fmaxf(mt0, fmaxf(s[nt][0], s[nt][1]));
            mt1 = fmaxf(mt1, fmaxf(s[nt][2], s[nt][3]));
        }
        mt0 = fmaxf(mt0, __shfl_xor_sync(0xffffffffu, mt0, 1));
        mt0 = fmaxf(mt0, __shfl_xor_sync(0xffffffffu, mt0, 2));
        mt1 = fmaxf(mt1, __shfl_xor_sync(0xffffffffu, mt1, 1));
        mt1 = fmaxf(mt1, __shfl_xor_sync(0xffffffffu, mt1, 2));

        float mn0 = fmaxf(mrow[0], mt0);
        float mn1 = fmaxf(mrow[1], mt1);
        float al0 = __expf(mrow[0] - mn0);
        float al1 = __expf(mrow[1] - mn1);
        mrow[0] = mn0; mrow[1] = mn1;
        lrow[0] *= al0; lrow[1] *= al1;
#pragma unroll
        for (int j = 0; j < 8; ++j) {
            o[j][0] *= al0; o[j][1] *= al0;
            o[j][2] *= al1; o[j][3] *= al1;
        }

        float rs0 = 0.f, rs1 = 0.f;
#pragma unroll
        for (int nt = 0; nt < 8; ++nt) {
            s[nt][0] = to_tf32(__expf(s[nt][0] - mrow[0]));
            s[nt][1] = to_tf32(__expf(s[nt][1] - mrow[0]));
            s[nt][2] = to_tf32(__expf(s[nt][2] - mrow[1]));
            s[nt][3] = to_tf32(__expf(s[nt][3] - mrow[1]));
            rs0 += s[nt][0] + s[nt][1];
            rs1 += s[nt][2] + s[nt][3];
        }
        rs0 += __shfl_xor_sync(0xffffffffu, rs0, 1);
        rs0 += __shfl_xor_sync(0xffffffffu, rs0, 2);
        rs1 += __shfl_xor_sync(0xffffffffu, rs1, 1);
        rs1 += __shfl_xor_sync(0xffffffffu, rs1, 2);
        lrow[0] += rs0;
        lrow[1] += rs1;

        // P relayout C-frag -> A-frag via quad shuffles (bit-exact).
        // P(gid, c): src lane = gid*4 + (c>>1), reg parity = c&1.
        unsigned pa[8][4];
        bool odd = (tig & 1) != 0;
#pragma unroll
        for (int kk = 0; kk < 8; ++kk) {
            float e0 = __shfl_sync(0xffffffffu, s[kk][0], srcl);
            float o0 = __shfl_sync(0xffffffffu, s[kk][1], srcl);
            float e1 = __shfl_sync(0xffffffffu, s[kk][2], srcl);
            float o1 = __shfl_sync(0xffffffffu, s[kk][3], srcl);
            float e2 = __shfl_sync(0xffffffffu, s[kk][0], srcl + 2);
            float o2 = __shfl_sync(0xffffffffu, s[kk][1], srcl + 2);
            float e3 = __shfl_sync(0xffffffffu, s[kk][2], srcl + 2);
            float o3 = __shfl_sync(0xffffffffu, s[kk][3], srcl + 2);
            pa[kk][0] = __float_as_uint(odd ? o0 : e0);
            pa[kk][1] = __float_as_uint(odd ? o1 : e1);
            pa[kk][2] = __float_as_uint(odd ? o2 : e2);
            pa[kk][3] = __float_as_uint(odd ? o3 : e3);
        }

        // O += P @ V : V B-fragments via ldmatrix
#pragma unroll
        for (int j = 0; j < 8; ++j) {
#pragma unroll
            for (int kp = 0; kp < 4; ++kp) {
                unsigned bf[4];
                ldsm_x4(bf, &Vp[(j * 8 + l8) * VP + kp * 16 + bh4]);
                mma_tf32(o[j], pa[2 * kp],     bf[0], bf[1]);
                mma_tf32(o[j], pa[2 * kp + 1], bf[2], bf[3]);
            }
        }
    }

    float inv0 = 1.f / lrow[0];
    float inv1 = 1.f / lrow[1];
    int r0 = q0 + w * 16 + gid;
#pragma unroll
    for (int j = 0; j < 8; ++j) {
        int col = h * NDH + j * 8 + 2 * tig;
        *(float2*)&out[((size_t)(b * NS + r0)) * NDV + col] =
            make_float2(o[j][0] * inv0, o[j][1] * inv0);
        *(float2*)&out[((size_t)(b * NS + r0 + 8)) * NDV + col] =
            make_float2(o[j][2] * inv1, o[j][3] * inv1);
    }
}

// ---------------------------------------------------------------------------
// Launch
// ---------------------------------------------------------------------------
extern "C" void kernel_launch(void* const* d_in, const int* in_sizes, int n_in,
                              void* d_out, int out_size) {
    const float* hid   = (const float*)d_in[0];
    const float* amask = (const float*)d_in[1];
    const float* txt   = (const float*)d_in[2];
    const float* tmask = (const float*)d_in[3];
    const float* Wq  = (const float*)d_in[4];
    const float* bq  = (const float*)d_in[5];
    const float* Wk  = (const float*)d_in[6];
    const float* bk  = (const float*)d_in[7];
    const float* Wv  = (const float*)d_in[8];
    const float* bv  = (const float*)d_in[9];
    const float* Wdq = (const float*)d_in[10];
    const float* bdq = (const float*)d_in[11];
    const float* Wdk = (const float*)d_in[12];
    const float* bdk = (const float*)d_in[13];
    float* out = (float*)d_out;

    cudaFuncSetAttribute(attn_kernel,
                         cudaFuncAttributeMaxDynamicSharedMemorySize,
                         ATTN_SMEM_BYTES);
    cudaFuncSetAttribute(qkv_kernel,
                         cudaFuncAttributeMaxDynamicSharedMemorySize,
                         QKV_SMEM_BYTES);

    wt_kernel<<<dim3(NDV / 32, NDV / 32, 3), dim3(32, 8)>>>(Wq, Wk, Wv);
    pool_kernel<<<(NB * NDT + 255) / 256, 256>>>(txt, tmask);
    gate_kernel<<<dim3((NB * NDV + 255) / 256, 2), 256>>>(Wdq, bdq, Wdk, bdk);
    qkv_kernel<<<dim3(NDV / 128, (NB * NS) / 128, 3), 256, QKV_SMEM_BYTES>>>(
        hid, bq, bk, bv);
    attn_kernel<<<dim3(NS / BQ, NB * NH), 128, ATTN_SMEM_BYTES>>>(amask, out);
}